// round 2
// baseline (speedup 1.0000x reference)
#include <cuda_runtime.h>
#include <math.h>

#define NN 64
#define CC 64
#define TT_ 128
#define VV 25

// ---------------- device scratch ----------------
__device__ float g_x1[NN*8*TT_*VV];
__device__ float g_A12[NN*150];
__device__ float g_att[NN*36];
__device__ float g_att2[NN*625];
__device__ float g_x1gcn[NN*8*TT_*6];
__device__ float g_ysm[NN*8*TT_*6];
__device__ float g_ybarS[NN*6];
__device__ float g_y1[NN*CC*TT_*VV];
__device__ float g_y1sum_nv[NN*VV];
__device__ float g_y1sum_nc[NN*CC];
__device__ float g_A12l[NN*150];
__device__ float g_gate[NN*CC];
__device__ float g_SY[CC], g_SYY[CC];
__device__ float g_scale[CC], g_shift[CC];
__device__ float g_WcombT[64*192];
__device__ float g_bcomb[192];
__device__ float g_WpMean[64], g_WsMean[64];
__device__ float g_bpMean[1], g_bsMean[1];
__device__ float g_nlp[864];
__device__ float g_nlA[15000];

__device__ const int c_joints[6] = {3, 20, 7, 11, 14, 18};

// ---------------- zero accumulators ----------------
__global__ void kzero() {
    int i = blockIdx.x * 256 + threadIdx.x;
    if (i < NN*CC) g_y1sum_nc[i] = 0.f;
    if (i < NN*VV) g_y1sum_nv[i] = 0.f;
    if (i < CC) { g_SY[i] = 0.f; g_SYY[i] = 0.f; }
}

// ---------------- K0: weight folding ----------------
__global__ void k0(const float* __restrict__ W2, const float* __restrict__ Ws,
                   const float* __restrict__ b2, const float* __restrict__ bs,
                   const float* __restrict__ Wp, const float* __restrict__ bp,
                   const float* __restrict__ Dpap, const float* __restrict__ pa,
                   const float* __restrict__ DecA, const float* __restrict__ A1buf) {
    int tid = threadIdx.x;
    for (int idx = tid; idx < 64*192; idx += 256) {
        int cj = idx / 192, r = idx % 192;
        float s = 0.f;
        for (int cm = 0; cm < 64; cm++) s += W2[r*64 + cm] * Ws[cm*64 + cj];
        g_WcombT[cj*192 + r] = s;
    }
    for (int r = tid; r < 192; r += 256) {
        float s = 0.f;
        for (int cm = 0; cm < 64; cm++) s += W2[r*64 + cm] * bs[cm];
        g_bcomb[r] = s + b2[r];
    }
    for (int ci = tid; ci < 64; ci += 256) {
        float s = 0.f;
        for (int o = 0; o < 8; o++) s += Wp[o*64 + ci];
        g_WpMean[ci] = s * (1.f/8.f);
        float s2 = 0.f;
        for (int c = 0; c < 64; c++) s2 += Ws[c*64 + ci];
        g_WsMean[ci] = s2 * (1.f/64.f);
    }
    if (tid == 0) {
        float s = 0.f; for (int o = 0; o < 8; o++) s += bp[o];
        g_bpMean[0] = s * (1.f/8.f);
        float s2 = 0.f; for (int c = 0; c < 64; c++) s2 += bs[c];
        g_bsMean[0] = s2 * (1.f/64.f);
    }
    for (int i = tid; i < 864; i += 256) g_nlp[i] = Dpap[i] + pa[i];
    for (int i = tid; i < 15000; i += 256) g_nlA[i] = A1buf[i] + DecA[i];
}

// ---------------- K1: x1 = conv(x, Wp) + bp ----------------
__global__ void k1(const float* __restrict__ x, const float* __restrict__ Wp,
                   const float* __restrict__ bp) {
    __shared__ float xt[6400];
    __shared__ float Wps[512];
    __shared__ float bps[8];
    int n = blockIdx.x, t0 = blockIdx.y * 4, tid = threadIdx.x;
    for (int i = tid; i < 6400; i += 256) {
        int ci = i / 100, p = i % 100;
        xt[i] = x[((n*64 + ci)*128 + t0)*25 + p];
    }
    for (int i = tid; i < 512; i += 256) Wps[i] = Wp[i];
    if (tid < 8) bps[tid] = bp[tid];
    __syncthreads();
    for (int idx = tid; idx < 800; idx += 256) {
        int o = idx / 100, p = idx % 100;
        float acc = bps[o];
        #pragma unroll 16
        for (int ci = 0; ci < 64; ci++) acc += Wps[o*64 + ci] * xt[ci*100 + p];
        g_x1[((n*8 + o)*128 + t0)*25 + p] = acc;
    }
}

// ---------------- K2: per-n stats + 3 softmaxes ----------------
__global__ void k2(const float* __restrict__ x,
                   const float* wt1p, const float* wt2p, const float* wtw1p,
                   const float* wtw2p, const float* wtw11p, const float* wtw21p) {
    __shared__ float xbs[1600];
    __shared__ float mb[25], xm2s[25], a1s[6], a2s[25], A12s[150], xms[6];
    int n = blockIdx.x, tid = threadIdx.x;
    for (int i = tid; i < 1600; i += 256) {
        int ci = i / 25, v = i % 25;
        const float* xp = x + ((long)(n*64 + ci)*128)*25 + v;
        float s = 0.f;
        #pragma unroll 8
        for (int t = 0; t < 128; t++) s += xp[t*25];
        xbs[i] = s;
    }
    __syncthreads();
    if (tid < 25) {
        float d1 = 0.f, d2 = 0.f;
        for (int ci = 0; ci < 64; ci++) {
            float xv = xbs[ci*25 + tid] * (1.f/128.f);
            d1 += xv * g_WpMean[ci];
            d2 += xv * g_WsMean[ci];
        }
        mb[tid] = d1 + g_bpMean[0];
        xm2s[tid] = d2 + g_bsMean[0];
    }
    __syncthreads();
    float wt1 = *wt1p, wt2 = *wt2p;
    if (tid < 25) a2s[tid] = fmaxf(wt2 * mb[tid], 0.f);
    if (tid < 6)  a1s[tid] = fmaxf(wt1 * mb[c_joints[tid]], 0.f);
    __syncthreads();
    if (tid < 25) {
        float e[6], mx = -1e30f;
        #pragma unroll
        for (int j = 0; j < 6; j++) { e[j] = a1s[j] * a2s[tid]; mx = fmaxf(mx, e[j]); }
        float sm = 0.f;
        #pragma unroll
        for (int j = 0; j < 6; j++) { e[j] = expf(e[j] - mx); sm += e[j]; }
        float inv = 1.f / sm;
        #pragma unroll
        for (int j = 0; j < 6; j++) {
            float v = e[j] * inv;
            A12s[j*25 + tid] = v;
            g_A12[n*150 + j*25 + tid] = v;
        }
    }
    __syncthreads();
    if (tid < 6) {
        float s = 0.f;
        for (int v = 0; v < 25; v++) s += mb[v] * A12s[tid*25 + v];
        xms[tid] = s;
    }
    __syncthreads();
    float wtw1 = *wtw1p, wtw2 = *wtw2p;
    if (tid < 6) {
        float r2w = fmaxf(wtw2 * xms[tid], 0.f);
        float e[6], mx = -1e30f;
        #pragma unroll
        for (int j = 0; j < 6; j++) { e[j] = fmaxf(wtw1 * xms[j], 0.f) * r2w; mx = fmaxf(mx, e[j]); }
        float sm = 0.f;
        #pragma unroll
        for (int j = 0; j < 6; j++) { e[j] = expf(e[j] - mx); sm += e[j]; }
        float inv = 1.f / sm;
        #pragma unroll
        for (int j = 0; j < 6; j++) g_att[n*36 + j*6 + tid] = e[j] * inv;
    }
    float wtw11 = *wtw11p, wtw21 = *wtw21p;
    if (tid < 25) {
        float r2w = fmaxf(wtw21 * xm2s[tid], 0.f);
        float e[25], mx = -1e30f;
        #pragma unroll
        for (int v = 0; v < 25; v++) { e[v] = fmaxf(wtw11 * xm2s[v], 0.f) * r2w; mx = fmaxf(mx, e[v]); }
        float sm = 0.f;
        #pragma unroll
        for (int v = 0; v < 25; v++) { e[v] = expf(e[v] - mx); sm += e[v]; }
        float inv = 1.f / sm;
        #pragma unroll
        for (int v = 0; v < 25; v++) g_att2[n*625 + v*25 + tid] = e[v] * inv;
    }
}

// ---------------- K3: x1_GCN = x1 @ A12^T ----------------
__global__ void k3() {
    __shared__ float A12s[150];
    int n = blockIdx.x, tid = threadIdx.x;
    for (int i = tid; i < 150; i += 256) A12s[i] = g_A12[n*150 + i];
    __syncthreads();
    for (int ot = tid; ot < 1024; ot += 256) {
        int o = ot >> 7, t = ot & 127;
        const float* xr = g_x1 + ((n*8 + o)*128 + t)*25;
        float xv[25];
        #pragma unroll
        for (int v = 0; v < 25; v++) xv[v] = xr[v];
        #pragma unroll
        for (int j = 0; j < 6; j++) {
            float s = 0.f;
            #pragma unroll
            for (int v = 0; v < 25; v++) s += xv[v] * A12s[j*25 + v];
            g_x1gcn[((n*8 + o)*128 + t)*6 + j] = s;
        }
    }
}

// ---------------- K4: small branch y + ybarS ----------------
__global__ void k4(const float* __restrict__ W1, const float* __restrict__ b1) {
    __shared__ float gcns[6144];
    __shared__ float W1s[192], b1s[24], Efb[864], yred[6];
    int n = blockIdx.x, tid = threadIdx.x;
    for (int i = tid; i < 6144; i += 256) gcns[i] = g_x1gcn[n*6144 + i];
    for (int i = tid; i < 192; i += 256) W1s[i] = W1[i];
    if (tid < 24) b1s[tid] = b1[tid];
    for (int i = tid; i < 864; i += 256) Efb[i] = 0.5f * g_att[n*36 + (i % 36)] + g_nlp[i];
    if (tid < 6) yred[tid] = 0.f;
    __syncthreads();
    float lsum[6] = {0.f, 0.f, 0.f, 0.f, 0.f, 0.f};
    for (int gt = tid; gt < 1024; gt += 256) {
        int g = gt >> 7, t = gt & 127;
        float mloc[3][6];
        #pragma unroll
        for (int k = 0; k < 3; k++) {
            const float* wrow = &W1s[(k*8 + g)*8];
            float bb = b1s[k*8 + g];
            #pragma unroll
            for (int j = 0; j < 6; j++) {
                float s = bb;
                #pragma unroll
                for (int o = 0; o < 8; o++) s += gcns[(o*128 + t)*6 + j] * wrow[o];
                mloc[k][j] = s;
            }
        }
        #pragma unroll
        for (int w = 0; w < 6; w++) {
            float s = 0.f;
            #pragma unroll
            for (int k = 0; k < 3; k++)
                #pragma unroll
                for (int j = 0; j < 6; j++)
                    s += mloc[k][j] * Efb[((k*8 + g)*6 + j)*6 + w];
            g_ysm[(n*8 + g)*768 + t*6 + w] = s;
            lsum[w] += s;
        }
    }
    #pragma unroll
    for (int w = 0; w < 6; w++) atomicAdd(&yred[w], lsum[w]);
    __syncthreads();
    if (tid < 6) g_ybarS[n*6 + tid] = yred[tid] * (1.f/1024.f);
}

// ---------------- K5: heavy y1 = m2 contracted with (nlA + 0.5*att2) ----------------
#define K5_SMEM_FLOATS (12288 + 16800 + 10752 + 3200 + 128)
__global__ void __launch_bounds__(512, 1) k5(const float* __restrict__ x) {
    extern __shared__ float sm[];
    float* Wcs = sm;               // [64][192]
    float* Ds  = Wcs + 12288;      // [8][75][28]
    float* m2s = Ds + 16800;       // [192][56]
    float* xt  = m2s + 10752;      // [64][50]
    float* red = xt + 3200;        // [128]
    int n = blockIdx.x, t0 = blockIdx.y * 2, tid = threadIdx.x;
    if (tid < 128) red[tid] = 0.f;
    for (int i = tid; i < 12288; i += 512) Wcs[i] = g_WcombT[i];
    for (int i = tid; i < 3200; i += 512) {
        int ci = i / 50, p = i % 50;
        xt[i] = x[((n*64 + ci)*128 + t0)*25 + p];
    }
    const float* at2 = g_att2 + n*625;
    for (int i = tid; i < 16800; i += 512) {
        int g = i / 2100, r = i % 2100, kv = r / 28, w = r % 28;
        float val = 0.f;
        if (w < 25) {
            int k = kv / 25, v = kv % 25;
            val = g_nlA[((k*8 + g)*25 + v)*25 + w] + 0.5f * at2[v*25 + w];
        }
        Ds[i] = val;
    }
    __syncthreads();
    // phase A: m2[r][p] = Wcomb[r,:] . x[:,p] + bcomb[r]  (8r x 2p register tile)
    const float4* W4 = reinterpret_cast<const float4*>(Wcs);
    for (int tile = tid; tile < 600; tile += 512) {
        int rq = tile % 24, pp = tile / 24;
        int p0 = pp * 2;
        float acc[8][2];
        #pragma unroll
        for (int i = 0; i < 8; i++) { acc[i][0] = 0.f; acc[i][1] = 0.f; }
        #pragma unroll 4
        for (int ci = 0; ci < 64; ci++) {
            float4 w0 = W4[ci*48 + rq*2];
            float4 w1 = W4[ci*48 + rq*2 + 1];
            float x0 = xt[ci*50 + p0], x1v = xt[ci*50 + p0 + 1];
            acc[0][0] += w0.x*x0; acc[0][1] += w0.x*x1v;
            acc[1][0] += w0.y*x0; acc[1][1] += w0.y*x1v;
            acc[2][0] += w0.z*x0; acc[2][1] += w0.z*x1v;
            acc[3][0] += w0.w*x0; acc[3][1] += w0.w*x1v;
            acc[4][0] += w1.x*x0; acc[4][1] += w1.x*x1v;
            acc[5][0] += w1.y*x0; acc[5][1] += w1.y*x1v;
            acc[6][0] += w1.z*x0; acc[6][1] += w1.z*x1v;
            acc[7][0] += w1.w*x0; acc[7][1] += w1.w*x1v;
        }
        int r0 = rq * 8;
        #pragma unroll
        for (int i = 0; i < 8; i++) {
            float bb = g_bcomb[r0 + i];
            #pragma unroll
            for (int j = 0; j < 2; j++) {
                int p = p0 + j, tt = p / 25, v = p % 25;
                m2s[(r0 + i)*56 + tt*28 + v] = acc[i][j] + bb;
            }
        }
    }
    __syncthreads();
    // phase B: y1[c,tt,w] = sum_{k,v} m2[k*64+c][tt,v] * Ds[c&7][k*25+v][w]
    for (int tile = tid; tile < 448; tile += 512) {
        int c = tile / 7, wq = tile % 7, w0 = wq * 4, g = c & 7;
        float4 A0 = make_float4(0,0,0,0), A1 = make_float4(0,0,0,0);
        #pragma unroll
        for (int k = 0; k < 3; k++) {
            const float* m2r = &m2s[(k*64 + c)*56];
            const float4* dr = reinterpret_cast<const float4*>(&Ds[(g*75 + k*25)*28 + w0]);
            #pragma unroll
            for (int v = 0; v < 25; v++) {
                float m0 = m2r[v], m1 = m2r[28 + v];
                float4 d = dr[v*7];
                A0.x += m0*d.x; A0.y += m0*d.y; A0.z += m0*d.z; A0.w += m0*d.w;
                A1.x += m1*d.x; A1.y += m1*d.y; A1.z += m1*d.z; A1.w += m1*d.w;
            }
        }
        int base = ((n*64 + c)*128 + t0)*25;
        float va0[4] = {A0.x, A0.y, A0.z, A0.w};
        float va1[4] = {A1.x, A1.y, A1.z, A1.w};
        float csum = 0.f;
        #pragma unroll
        for (int j = 0; j < 4; j++) {
            int w = w0 + j;
            if (w < 25) {
                g_y1[base + w] = va0[j];
                g_y1[base + 25 + w] = va1[j];
                float sw = va0[j] + va1[j];
                atomicAdd(&red[w], sw);
                csum += sw;
            }
        }
        atomicAdd(&red[32 + c], csum);
    }
    __syncthreads();
    if (tid < 25) atomicAdd(&g_y1sum_nv[n*25 + tid], red[tid]);
    if (tid >= 32 && tid < 96) atomicAdd(&g_y1sum_nc[n*64 + tid - 32], red[tid]);
}

// ---------------- K6: A12l + channel gate ----------------
__global__ void k6(const float* ws1p, const float* ws2p,
                   const float* __restrict__ We, const float* __restrict__ be,
                   const float* __restrict__ kca) {
    __shared__ float a1ls[6], A12ls[150], ytsum[48], Asum[6], Ssum[8], qs[64];
    int n = blockIdx.x, tid = threadIdx.x;
    if (tid < 6) a1ls[tid] = fmaxf((*ws1p) * g_ybarS[n*6 + tid], 0.f);
    __syncthreads();
    if (tid < 25) {
        float a2 = fmaxf((*ws2p) * g_y1sum_nv[n*25 + tid] * (1.f/8192.f), 0.f);
        float e[6], mx = -1e30f;
        #pragma unroll
        for (int j = 0; j < 6; j++) { e[j] = a1ls[j] * a2; mx = fmaxf(mx, e[j]); }
        float s = 0.f;
        #pragma unroll
        for (int j = 0; j < 6; j++) { e[j] = expf(e[j] - mx); s += e[j]; }
        float inv = 1.f / s;
        #pragma unroll
        for (int j = 0; j < 6; j++) {
            float v = e[j] * inv;
            A12ls[j*25 + tid] = v;
            g_A12l[n*150 + j*25 + tid] = v;
        }
    }
    for (int i = tid; i < 48; i += 128) {
        int o = i / 6, j = i % 6;
        float s = 0.f;
        for (int t = 0; t < 128; t++) s += g_ysm[(n*8 + o)*768 + t*6 + j];
        ytsum[i] = s;
    }
    __syncthreads();
    if (tid < 6) {
        float s = 0.f;
        for (int v = 0; v < 25; v++) s += A12ls[tid*25 + v];
        Asum[tid] = s;
    }
    __syncthreads();
    if (tid < 8) {
        float s = 0.f;
        #pragma unroll
        for (int j = 0; j < 6; j++) s += ytsum[tid*6 + j] * Asum[j];
        Ssum[tid] = s;
    }
    __syncthreads();
    if (tid < 64) {
        float yls = 3200.f * be[tid];
        #pragma unroll
        for (int o = 0; o < 8; o++) yls += We[tid*8 + o] * Ssum[o];
        qs[tid] = (g_y1sum_nc[n*64 + tid] + 0.5f * yls) * (1.f/3200.f);
    }
    __syncthreads();
    if (tid < 64) {
        float qm = (tid > 0) ? qs[tid-1] : 0.f;
        float q0 = qs[tid];
        float qp1 = (tid < 63) ? qs[tid+1] : 0.f;
        float qc = kca[0]*qm + kca[1]*q0 + kca[2]*qp1;
        g_gate[n*64 + tid] = 1.f + 1.f/(1.f + expf(-qc));
    }
}

// ---------------- K7: Y = (0.5*yl + y1)*gate, BN stats ----------------
__global__ void k7(const float* __restrict__ We, const float* __restrict__ be) {
    __shared__ float A12ls[150], Wes[512], bes[64], gates[64], ytile[768], zs[3200];
    int n = blockIdx.x, t0 = blockIdx.y * 16, tid = threadIdx.x;
    for (int i = tid; i < 150; i += 256) A12ls[i] = g_A12l[n*150 + i];
    for (int i = tid; i < 512; i += 256) Wes[i] = We[i];
    if (tid < 64) { bes[tid] = be[tid]; gates[tid] = g_gate[n*64 + tid]; }
    for (int i = tid; i < 768; i += 256) {
        int o = i / 96, r = i % 96, t = r / 6, j = r % 6;
        ytile[i] = g_ysm[(n*8 + o)*768 + (t0 + t)*6 + j];
    }
    __syncthreads();
    for (int i = tid; i < 3200; i += 256) {
        int o = i / 400, r = i % 400, t = r / 25, v = r % 25;
        float s = 0.f;
        #pragma unroll
        for (int j = 0; j < 6; j++) s += ytile[o*96 + t*6 + j] * A12ls[j*25 + v];
        zs[i] = s;
    }
    __syncthreads();
    int c = tid >> 2, sub = tid & 3;
    float wrow[8];
    #pragma unroll
    for (int o = 0; o < 8; o++) wrow[o] = Wes[c*8 + o];
    float bc = bes[c], gt = gates[c];
    float lsy = 0.f, lsyy = 0.f;
    for (int i = sub; i < 400; i += 4) {
        int t = i / 25, v = i % 25;
        float yl = bc;
        #pragma unroll
        for (int o = 0; o < 8; o++) yl += wrow[o] * zs[o*400 + i];
        int idx = ((n*64 + c)*128 + t0 + t)*25 + v;
        float Y = 0.5f*yl + g_y1[idx];
        float Yg = Y * gt;
        g_y1[idx] = Yg;
        lsy += Yg;
        lsyy += Yg * Yg;
    }
    #pragma unroll
    for (int off = 1; off < 4; off <<= 1) {
        lsy  += __shfl_down_sync(0xffffffffu, lsy, off);
        lsyy += __shfl_down_sync(0xffffffffu, lsyy, off);
    }
    if (sub == 0) {
        atomicAdd(&g_SY[c], lsy);
        atomicAdd(&g_SYY[c], lsyy);
    }
}

// ---------------- K8: BN finalize ----------------
__global__ void k8(const float* __restrict__ bn_g, const float* __restrict__ bn_b) {
    int c = threadIdx.x;
    if (c < 64) {
        const float cnt = 204800.f;
        float mu = g_SY[c] / cnt;
        float var = g_SYY[c] / cnt - mu*mu;
        float sc = bn_g[c] * rsqrtf(var + 1e-5f);
        g_scale[c] = sc;
        g_shift[c] = bn_b[c] - mu*sc;
    }
}

// ---------------- K9: out = relu(BN(Yg) + x) ----------------
__global__ void k9(const float* __restrict__ x, float* __restrict__ out) {
    int i = blockIdx.x * 256 + threadIdx.x;    // float4 index
    if (i >= 3276800) return;
    int c = (i / 800) & 63;
    float4 yv = reinterpret_cast<const float4*>(g_y1)[i];
    float4 xv = reinterpret_cast<const float4*>(x)[i];
    float sc = g_scale[c], sh = g_shift[c];
    float4 o;
    o.x = fmaxf(yv.x*sc + sh + xv.x, 0.f);
    o.y = fmaxf(yv.y*sc + sh + xv.y, 0.f);
    o.z = fmaxf(yv.z*sc + sh + xv.z, 0.f);
    o.w = fmaxf(yv.w*sc + sh + xv.w, 0.f);
    reinterpret_cast<float4*>(out)[i] = o;
}

// ---------------- launch ----------------
extern "C" void kernel_launch(void* const* d_in, const int* in_sizes, int n_in,
                              void* d_out, int out_size) {
    const float* x     = (const float*)d_in[0];
    const float* Dpap  = (const float*)d_in[1];
    const float* pa    = (const float*)d_in[2];
    const float* DecA  = (const float*)d_in[3];
    const float* A1buf = (const float*)d_in[4];
    const float* Wp    = (const float*)d_in[5];
    const float* bp    = (const float*)d_in[6];
    const float* Ws    = (const float*)d_in[7];
    const float* bs    = (const float*)d_in[8];
    const float* W1    = (const float*)d_in[9];
    const float* b1    = (const float*)d_in[10];
    const float* W2    = (const float*)d_in[11];
    const float* b2    = (const float*)d_in[12];
    const float* We    = (const float*)d_in[13];
    const float* be    = (const float*)d_in[14];
    const float* wt1   = (const float*)d_in[15];
    const float* wt2   = (const float*)d_in[16];
    const float* wtw1  = (const float*)d_in[17];
    const float* wtw2  = (const float*)d_in[18];
    const float* wtw11 = (const float*)d_in[19];
    const float* wtw21 = (const float*)d_in[20];
    const float* ws1   = (const float*)d_in[21];
    const float* ws2   = (const float*)d_in[22];
    const float* kca   = (const float*)d_in[23];
    const float* bn_g  = (const float*)d_in[24];
    const float* bn_b  = (const float*)d_in[25];
    float* out = (float*)d_out;

    cudaFuncSetAttribute(k5, cudaFuncAttributeMaxDynamicSharedMemorySize,
                         K5_SMEM_FLOATS * 4);

    kzero<<<16, 256>>>();
    k0<<<1, 256>>>(W2, Ws, b2, bs, Wp, bp, Dpap, pa, DecA, A1buf);
    k1<<<dim3(64, 32), 256>>>(x, Wp, bp);
    k2<<<64, 256>>>(x, wt1, wt2, wtw1, wtw2, wtw11, wtw21);
    k3<<<64, 256>>>();
    k4<<<64, 256>>>(W1, b1);
    k5<<<dim3(64, 64), 512, K5_SMEM_FLOATS * 4>>>(x);
    k6<<<64, 128>>>(ws1, ws2, We, be, kca);
    k7<<<dim3(64, 8), 256>>>(We, be);
    k8<<<1, 64>>>(bn_g, bn_b);
    k9<<<12800, 256>>>(x, out);
}

// round 3
// speedup vs baseline: 1.3932x; 1.3932x over previous
#include <cuda_runtime.h>
#include <math.h>

#define NN 64
#define CC 64
#define TT_ 128
#define VV 25

// ---------------- device scratch ----------------
__device__ float g_x1[NN*8*TT_*VV];
__device__ float g_xbar[NN*1600];
__device__ float g_A12[NN*150];
__device__ float g_att[NN*36];
__device__ float g_att2[NN*625];
__device__ float g_x1gcn[NN*8*TT_*6];
__device__ float g_ysm[NN*8*TT_*6];
__device__ float g_ybarS[NN*6];
__device__ float g_y1[NN*CC*TT_*VV];
__device__ float g_y1sum_nv[NN*VV];
__device__ float g_y1sum_nc[NN*CC];
__device__ float g_A12l[NN*150];
__device__ float g_gate[NN*CC];
__device__ float g_SY[CC], g_SYY[CC];
__device__ float g_scale[CC], g_shift[CC];
__device__ float g_WcombT[64*192];
__device__ float g_bcomb[192];
__device__ float g_WpMean[64], g_WsMean[64];
__device__ float g_bpMean[1], g_bsMean[1];
__device__ float g_nlp[864];
__device__ float g_nlA[15000];

__device__ const int c_joints[6] = {3, 20, 7, 11, 14, 18};

// ---------------- zero accumulators ----------------
__global__ void kzero() {
    int i = blockIdx.x * 256 + threadIdx.x;
    if (i < NN*1600) g_xbar[i] = 0.f;
    if (i < NN*CC) g_y1sum_nc[i] = 0.f;
    if (i < NN*VV) g_y1sum_nv[i] = 0.f;
    if (i < CC) { g_SY[i] = 0.f; g_SYY[i] = 0.f; }
}

// ---------------- K0: weight folding ----------------
__global__ void k0(const float* __restrict__ W2, const float* __restrict__ Ws,
                   const float* __restrict__ b2, const float* __restrict__ bs,
                   const float* __restrict__ Wp, const float* __restrict__ bp,
                   const float* __restrict__ Dpap, const float* __restrict__ pa,
                   const float* __restrict__ DecA, const float* __restrict__ A1buf) {
    int tid = threadIdx.x;
    for (int idx = tid; idx < 64*192; idx += 256) {
        int cj = idx / 192, r = idx % 192;
        float s = 0.f;
        for (int cm = 0; cm < 64; cm++) s += W2[r*64 + cm] * Ws[cm*64 + cj];
        g_WcombT[cj*192 + r] = s;
    }
    for (int r = tid; r < 192; r += 256) {
        float s = 0.f;
        for (int cm = 0; cm < 64; cm++) s += W2[r*64 + cm] * bs[cm];
        g_bcomb[r] = s + b2[r];
    }
    for (int ci = tid; ci < 64; ci += 256) {
        float s = 0.f;
        for (int o = 0; o < 8; o++) s += Wp[o*64 + ci];
        g_WpMean[ci] = s * (1.f/8.f);
        float s2 = 0.f;
        for (int c = 0; c < 64; c++) s2 += Ws[c*64 + ci];
        g_WsMean[ci] = s2 * (1.f/64.f);
    }
    if (tid == 0) {
        float s = 0.f; for (int o = 0; o < 8; o++) s += bp[o];
        g_bpMean[0] = s * (1.f/8.f);
        float s2 = 0.f; for (int c = 0; c < 64; c++) s2 += bs[c];
        g_bsMean[0] = s2 * (1.f/64.f);
    }
    for (int i = tid; i < 864; i += 256) g_nlp[i] = Dpap[i] + pa[i];
    for (int i = tid; i < 15000; i += 256) g_nlA[i] = A1buf[i] + DecA[i];
}

// ---------------- K1: x1 conv + xbar partial sums ----------------
__global__ void k1(const float* __restrict__ x, const float* __restrict__ Wp,
                   const float* __restrict__ bp) {
    __shared__ float xt[6400];   // [ci][100]
    __shared__ float Wps[512];
    __shared__ float bps[8];
    int n = blockIdx.x, t0 = blockIdx.y * 4, tid = threadIdx.x;
    const float4* x4 = reinterpret_cast<const float4*>(x);
    float4* xt4 = reinterpret_cast<float4*>(xt);
    int xbase4 = n*51200 + (t0/4)*25;
    for (int i = tid; i < 1600; i += 256) {
        int ci = i / 25, p4 = i % 25;
        xt4[ci*25 + p4] = x4[xbase4 + ci*800 + p4];
    }
    for (int i = tid; i < 512; i += 256) Wps[i] = Wp[i];
    if (tid < 8) bps[tid] = bp[tid];
    __syncthreads();
    for (int idx = tid; idx < 800; idx += 256) {
        int o = idx / 100, p = idx % 100;
        float acc = bps[o];
        #pragma unroll 16
        for (int ci = 0; ci < 64; ci++) acc += Wps[o*64 + ci] * xt[ci*100 + p];
        g_x1[((n*8 + o)*128 + t0)*25 + p] = acc;
    }
    for (int i = tid; i < 1600; i += 256) {
        int ci = i / 25, v = i % 25;
        float s = xt[ci*100 + v] + xt[ci*100 + 25 + v]
                + xt[ci*100 + 50 + v] + xt[ci*100 + 75 + v];
        atomicAdd(&g_xbar[n*1600 + i], s);
    }
}

// ---------------- K2: per-n stats + 3 softmaxes (no x read) ----------------
__global__ void k2(const float* wt1p, const float* wt2p, const float* wtw1p,
                   const float* wtw2p, const float* wtw11p, const float* wtw21p) {
    __shared__ float xbs[1600];
    __shared__ float mb[25], xm2s[25], a1s[6], a2s[25], A12s[150], xms[6];
    int n = blockIdx.x, tid = threadIdx.x;
    for (int i = tid; i < 1600; i += 256) xbs[i] = g_xbar[n*1600 + i];
    __syncthreads();
    if (tid < 25) {
        float d1 = 0.f, d2 = 0.f;
        for (int ci = 0; ci < 64; ci++) {
            float xv = xbs[ci*25 + tid] * (1.f/128.f);
            d1 += xv * g_WpMean[ci];
            d2 += xv * g_WsMean[ci];
        }
        mb[tid] = d1 + g_bpMean[0];
        xm2s[tid] = d2 + g_bsMean[0];
    }
    __syncthreads();
    float wt1 = *wt1p, wt2 = *wt2p;
    if (tid < 25) a2s[tid] = fmaxf(wt2 * mb[tid], 0.f);
    if (tid < 6)  a1s[tid] = fmaxf(wt1 * mb[c_joints[tid]], 0.f);
    __syncthreads();
    if (tid < 25) {
        float e[6], mx = -1e30f;
        #pragma unroll
        for (int j = 0; j < 6; j++) { e[j] = a1s[j] * a2s[tid]; mx = fmaxf(mx, e[j]); }
        float sm = 0.f;
        #pragma unroll
        for (int j = 0; j < 6; j++) { e[j] = expf(e[j] - mx); sm += e[j]; }
        float inv = 1.f / sm;
        #pragma unroll
        for (int j = 0; j < 6; j++) {
            float v = e[j] * inv;
            A12s[j*25 + tid] = v;
            g_A12[n*150 + j*25 + tid] = v;
        }
    }
    __syncthreads();
    if (tid < 6) {
        float s = 0.f;
        for (int v = 0; v < 25; v++) s += mb[v] * A12s[tid*25 + v];
        xms[tid] = s;
    }
    __syncthreads();
    float wtw1 = *wtw1p, wtw2 = *wtw2p;
    if (tid < 6) {
        float r2w = fmaxf(wtw2 * xms[tid], 0.f);
        float e[6], mx = -1e30f;
        #pragma unroll
        for (int j = 0; j < 6; j++) { e[j] = fmaxf(wtw1 * xms[j], 0.f) * r2w; mx = fmaxf(mx, e[j]); }
        float sm = 0.f;
        #pragma unroll
        for (int j = 0; j < 6; j++) { e[j] = expf(e[j] - mx); sm += e[j]; }
        float inv = 1.f / sm;
        #pragma unroll
        for (int j = 0; j < 6; j++) g_att[n*36 + j*6 + tid] = e[j] * inv;
    }
    float wtw11 = *wtw11p, wtw21 = *wtw21p;
    if (tid < 25) {
        float r2w = fmaxf(wtw21 * xm2s[tid], 0.f);
        float e[25], mx = -1e30f;
        #pragma unroll
        for (int v = 0; v < 25; v++) { e[v] = fmaxf(wtw11 * xm2s[v], 0.f) * r2w; mx = fmaxf(mx, e[v]); }
        float sm = 0.f;
        #pragma unroll
        for (int v = 0; v < 25; v++) { e[v] = expf(e[v] - mx); sm += e[v]; }
        float inv = 1.f / sm;
        #pragma unroll
        for (int v = 0; v < 25; v++) g_att2[n*625 + v*25 + tid] = e[v] * inv;
    }
}

// ---------------- K3: x1_GCN = x1 @ A12^T ----------------
__global__ void k3() {
    __shared__ float A12s[150];
    int n = blockIdx.x, tid = threadIdx.x;
    for (int i = tid; i < 150; i += 256) A12s[i] = g_A12[n*150 + i];
    __syncthreads();
    for (int ot = tid; ot < 1024; ot += 256) {
        int o = ot >> 7, t = ot & 127;
        const float* xr = g_x1 + ((n*8 + o)*128 + t)*25;
        float xv[25];
        #pragma unroll
        for (int v = 0; v < 25; v++) xv[v] = xr[v];
        #pragma unroll
        for (int j = 0; j < 6; j++) {
            float s = 0.f;
            #pragma unroll
            for (int v = 0; v < 25; v++) s += xv[v] * A12s[j*25 + v];
            g_x1gcn[((n*8 + o)*128 + t)*6 + j] = s;
        }
    }
}

// ---------------- K4: small branch y + ybarS ----------------
__global__ void k4(const float* __restrict__ W1, const float* __restrict__ b1) {
    __shared__ float gcns[6144];
    __shared__ float W1s[192], b1s[24], Efb[864], yred[6];
    int n = blockIdx.x, tid = threadIdx.x;
    for (int i = tid; i < 6144; i += 256) gcns[i] = g_x1gcn[n*6144 + i];
    for (int i = tid; i < 192; i += 256) W1s[i] = W1[i];
    if (tid < 24) b1s[tid] = b1[tid];
    for (int i = tid; i < 864; i += 256) Efb[i] = 0.5f * g_att[n*36 + (i % 36)] + g_nlp[i];
    if (tid < 6) yred[tid] = 0.f;
    __syncthreads();
    float lsum[6] = {0.f, 0.f, 0.f, 0.f, 0.f, 0.f};
    for (int gt = tid; gt < 1024; gt += 256) {
        int g = gt >> 7, t = gt & 127;
        float mloc[3][6];
        #pragma unroll
        for (int k = 0; k < 3; k++) {
            const float* wrow = &W1s[(k*8 + g)*8];
            float bb = b1s[k*8 + g];
            #pragma unroll
            for (int j = 0; j < 6; j++) {
                float s = bb;
                #pragma unroll
                for (int o = 0; o < 8; o++) s += gcns[(o*128 + t)*6 + j] * wrow[o];
                mloc[k][j] = s;
            }
        }
        #pragma unroll
        for (int w = 0; w < 6; w++) {
            float s = 0.f;
            #pragma unroll
            for (int k = 0; k < 3; k++)
                #pragma unroll
                for (int j = 0; j < 6; j++)
                    s += mloc[k][j] * Efb[((k*8 + g)*6 + j)*6 + w];
            g_ysm[(n*8 + g)*768 + t*6 + w] = s;
            lsum[w] += s;
        }
    }
    #pragma unroll
    for (int w = 0; w < 6; w++) atomicAdd(&yred[w], lsum[w]);
    __syncthreads();
    if (tid < 6) g_ybarS[n*6 + tid] = yred[tid] * (1.f/1024.f);
}

// ---------------- K5: heavy y1 kernel (t-tile=4) ----------------
// smem: Wcs[64*192] | Ds[8*75*28] | m2s[192*104] | xt[64*100] | red[128] | bcs[192]
#define K5_SMEM_FLOATS (12288 + 16800 + 19968 + 6400 + 128 + 192)
__global__ void __launch_bounds__(512, 1) k5(const float* __restrict__ x) {
    extern __shared__ float sm[];
    float* Wcs = sm;
    float* Ds  = Wcs + 12288;
    float* m2s = Ds + 16800;
    float* xt  = m2s + 19968;
    float* red = xt + 6400;
    float* bcs = red + 128;
    int n = blockIdx.x, t0 = blockIdx.y * 4, tid = threadIdx.x;
    if (tid < 128) red[tid] = 0.f;
    if (tid < 192) bcs[tid] = g_bcomb[tid];
    {
        const float4* Wg4 = reinterpret_cast<const float4*>(g_WcombT);
        float4* Ws4 = reinterpret_cast<float4*>(Wcs);
        for (int i = tid; i < 3072; i += 512) Ws4[i] = Wg4[i];
        const float4* x4 = reinterpret_cast<const float4*>(x);
        float4* xt4 = reinterpret_cast<float4*>(xt);
        int xbase4 = n*51200 + (t0/4)*25;
        for (int i = tid; i < 1600; i += 512) {
            int ci = i / 25, p4 = i % 25;
            xt4[ci*25 + p4] = x4[xbase4 + ci*800 + p4];
        }
    }
    const float* at2 = g_att2 + n*625;
    for (int i = tid; i < 16800; i += 512) {
        int g = i / 2100, r = i % 2100, kv = r / 28, w = r % 28;
        float val = 0.f;
        if (w < 25) {
            int k = kv / 25, v = kv % 25;
            val = g_nlA[((k*8 + g)*25 + v)*25 + w] + 0.5f * at2[v*25 + w];
        }
        Ds[i] = val;
    }
    __syncthreads();
    // phase A: m2[r][p] for 192 r x 100 p ; tile = 8r x 4p
    {
        const float4* W4 = reinterpret_cast<const float4*>(Wcs);
        const float4* xt4 = reinterpret_cast<const float4*>(xt);
        for (int tile = tid; tile < 600; tile += 512) {
            int rq = tile % 24, pp = tile / 24;
            float acc[8][4];
            #pragma unroll
            for (int i = 0; i < 8; i++)
                #pragma unroll
                for (int j = 0; j < 4; j++) acc[i][j] = 0.f;
            #pragma unroll 8
            for (int ci = 0; ci < 64; ci++) {
                float4 w0 = W4[ci*48 + rq*2];
                float4 w1 = W4[ci*48 + rq*2 + 1];
                float4 xv = xt4[ci*25 + pp];
                float xa[4] = {xv.x, xv.y, xv.z, xv.w};
                float wa[8] = {w0.x, w0.y, w0.z, w0.w, w1.x, w1.y, w1.z, w1.w};
                #pragma unroll
                for (int i = 0; i < 8; i++)
                    #pragma unroll
                    for (int j = 0; j < 4; j++) acc[i][j] += wa[i]*xa[j];
            }
            int r0 = rq * 8, p0 = pp * 4;
            #pragma unroll
            for (int i = 0; i < 8; i++) {
                float bb = bcs[r0 + i];
                #pragma unroll
                for (int j = 0; j < 4; j++) {
                    int p = p0 + j, tt = p / 25, v = p % 25;
                    m2s[(r0 + i)*104 + tt*26 + v] = acc[i][j] + bb;
                }
            }
        }
    }
    __syncthreads();
    // phase B: tiles = (cpair, wq): 32*7 = 224; each 2c x 4t x 4w
    if (tid < 224) {
        int cp = tid / 7, wq = tid % 7, w0 = wq * 4;
        int g = cp & 7, q = cp >> 3;
        int ca = g + q*16, cb = ca + 8;
        float acca[4][4], accb[4][4];
        #pragma unroll
        for (int tt = 0; tt < 4; tt++)
            #pragma unroll
            for (int j = 0; j < 4; j++) { acca[tt][j] = 0.f; accb[tt][j] = 0.f; }
        #pragma unroll
        for (int k = 0; k < 3; k++) {
            const float* ma = &m2s[(k*64 + ca)*104];
            const float* mb = &m2s[(k*64 + cb)*104];
            const float4* dr = reinterpret_cast<const float4*>(&Ds[(g*75 + k*25)*28 + w0]);
            #pragma unroll 5
            for (int v = 0; v < 25; v++) {
                float4 d = dr[v*7];
                float da[4] = {d.x, d.y, d.z, d.w};
                #pragma unroll
                for (int tt = 0; tt < 4; tt++) {
                    float va = ma[tt*26 + v], vb = mb[tt*26 + v];
                    #pragma unroll
                    for (int j = 0; j < 4; j++) {
                        acca[tt][j] += va * da[j];
                        accb[tt][j] += vb * da[j];
                    }
                }
            }
        }
        int basea = ((n*64 + ca)*128 + t0)*25;
        int baseb = ((n*64 + cb)*128 + t0)*25;
        float csa = 0.f, csb = 0.f;
        #pragma unroll
        for (int j = 0; j < 4; j++) {
            int w = w0 + j;
            if (w < 25) {
                float ws = 0.f;
                #pragma unroll
                for (int tt = 0; tt < 4; tt++) {
                    g_y1[basea + tt*25 + w] = acca[tt][j];
                    g_y1[baseb + tt*25 + w] = accb[tt][j];
                    ws += acca[tt][j] + accb[tt][j];
                    csa += acca[tt][j];
                    csb += accb[tt][j];
                }
                atomicAdd(&red[w], ws);
            }
        }
        atomicAdd(&red[32 + ca], csa);
        atomicAdd(&red[32 + cb], csb);
    }
    __syncthreads();
    if (tid < 25) atomicAdd(&g_y1sum_nv[n*25 + tid], red[tid]);
    if (tid >= 32 && tid < 96) atomicAdd(&g_y1sum_nc[n*64 + tid - 32], red[tid]);
}

// ---------------- K6: A12l + channel gate ----------------
__global__ void k6(const float* ws1p, const float* ws2p,
                   const float* __restrict__ We, const float* __restrict__ be,
                   const float* __restrict__ kca) {
    __shared__ float a1ls[6], A12ls[150], ytsum[48], Asum[6], Ssum[8], qs[64];
    int n = blockIdx.x, tid = threadIdx.x;
    if (tid < 6) a1ls[tid] = fmaxf((*ws1p) * g_ybarS[n*6 + tid], 0.f);
    __syncthreads();
    if (tid < 25) {
        float a2 = fmaxf((*ws2p) * g_y1sum_nv[n*25 + tid] * (1.f/8192.f), 0.f);
        float e[6], mx = -1e30f;
        #pragma unroll
        for (int j = 0; j < 6; j++) { e[j] = a1ls[j] * a2; mx = fmaxf(mx, e[j]); }
        float s = 0.f;
        #pragma unroll
        for (int j = 0; j < 6; j++) { e[j] = expf(e[j] - mx); s += e[j]; }
        float inv = 1.f / s;
        #pragma unroll
        for (int j = 0; j < 6; j++) {
            float v = e[j] * inv;
            A12ls[j*25 + tid] = v;
            g_A12l[n*150 + j*25 + tid] = v;
        }
    }
    for (int i = tid; i < 48; i += 128) {
        int o = i / 6, j = i % 6;
        float s = 0.f;
        for (int t = 0; t < 128; t++) s += g_ysm[(n*8 + o)*768 + t*6 + j];
        ytsum[i] = s;
    }
    __syncthreads();
    if (tid < 6) {
        float s = 0.f;
        for (int v = 0; v < 25; v++) s += A12ls[tid*25 + v];
        Asum[tid] = s;
    }
    __syncthreads();
    if (tid < 8) {
        float s = 0.f;
        #pragma unroll
        for (int j = 0; j < 6; j++) s += ytsum[tid*6 + j] * Asum[j];
        Ssum[tid] = s;
    }
    __syncthreads();
    if (tid < 64) {
        float yls = 3200.f * be[tid];
        #pragma unroll
        for (int o = 0; o < 8; o++) yls += We[tid*8 + o] * Ssum[o];
        qs[tid] = (g_y1sum_nc[n*64 + tid] + 0.5f * yls) * (1.f/3200.f);
    }
    __syncthreads();
    if (tid < 64) {
        float qm = (tid > 0) ? qs[tid-1] : 0.f;
        float q0 = qs[tid];
        float qp1 = (tid < 63) ? qs[tid+1] : 0.f;
        float qc = kca[0]*qm + kca[1]*q0 + kca[2]*qp1;
        g_gate[n*64 + tid] = 1.f + 1.f/(1.f + expf(-qc));
    }
}

// ---------------- K7: Y = (0.5*yl + y1)*gate, BN stats ----------------
__global__ void k7(const float* __restrict__ We, const float* __restrict__ be) {
    __shared__ float A12ls[150], Wes[512], bes[64], gates[64], ytile[768], zs[3200];
    int n = blockIdx.x, t0 = blockIdx.y * 16, tid = threadIdx.x;
    for (int i = tid; i < 150; i += 256) A12ls[i] = g_A12l[n*150 + i];
    for (int i = tid; i < 512; i += 256) Wes[i] = We[i];
    if (tid < 64) { bes[tid] = be[tid]; gates[tid] = g_gate[n*64 + tid]; }
    for (int i = tid; i < 768; i += 256) {
        int o = i / 96, r = i % 96, t = r / 6, j = r % 6;
        ytile[i] = g_ysm[(n*8 + o)*768 + (t0 + t)*6 + j];
    }
    __syncthreads();
    for (int i = tid; i < 3200; i += 256) {
        int o = i / 400, r = i % 400, t = r / 25, v = r % 25;
        float s = 0.f;
        #pragma unroll
        for (int j = 0; j < 6; j++) s += ytile[o*96 + t*6 + j] * A12ls[j*25 + v];
        zs[i] = s;
    }
    __syncthreads();
    int c = tid >> 2, sub = tid & 3;
    float wrow[8];
    #pragma unroll
    for (int o = 0; o < 8; o++) wrow[o] = Wes[c*8 + o];
    float bc = bes[c], gt = gates[c];
    float lsy = 0.f, lsyy = 0.f;
    for (int i = sub; i < 400; i += 4) {
        int t = i / 25, v = i % 25;
        float yl = bc;
        #pragma unroll
        for (int o = 0; o < 8; o++) yl += wrow[o] * zs[o*400 + i];
        int idx = ((n*64 + c)*128 + t0 + t)*25 + v;
        float Y = 0.5f*yl + g_y1[idx];
        float Yg = Y * gt;
        g_y1[idx] = Yg;
        lsy += Yg;
        lsyy += Yg * Yg;
    }
    #pragma unroll
    for (int off = 1; off < 4; off <<= 1) {
        lsy  += __shfl_down_sync(0xffffffffu, lsy, off);
        lsyy += __shfl_down_sync(0xffffffffu, lsyy, off);
    }
    if (sub == 0) {
        atomicAdd(&g_SY[c], lsy);
        atomicAdd(&g_SYY[c], lsyy);
    }
}

// ---------------- K8: BN finalize ----------------
__global__ void k8(const float* __restrict__ bn_g, const float* __restrict__ bn_b) {
    int c = threadIdx.x;
    if (c < 64) {
        const float cnt = 204800.f;
        float mu = g_SY[c] / cnt;
        float var = g_SYY[c] / cnt - mu*mu;
        float sc = bn_g[c] * rsqrtf(var + 1e-5f);
        g_scale[c] = sc;
        g_shift[c] = bn_b[c] - mu*sc;
    }
}

// ---------------- K9: out = relu(BN(Yg) + x) ----------------
__global__ void k9(const float* __restrict__ x, float* __restrict__ out) {
    int i = blockIdx.x * 256 + threadIdx.x;
    if (i >= 3276800) return;
    int c = (i / 800) & 63;
    float4 yv = reinterpret_cast<const float4*>(g_y1)[i];
    float4 xv = reinterpret_cast<const float4*>(x)[i];
    float sc = g_scale[c], sh = g_shift[c];
    float4 o;
    o.x = fmaxf(yv.x*sc + sh + xv.x, 0.f);
    o.y = fmaxf(yv.y*sc + sh + xv.y, 0.f);
    o.z = fmaxf(yv.z*sc + sh + xv.z, 0.f);
    o.w = fmaxf(yv.w*sc + sh + xv.w, 0.f);
    reinterpret_cast<float4*>(out)[i] = o;
}

// ---------------- launch ----------------
extern "C" void kernel_launch(void* const* d_in, const int* in_sizes, int n_in,
                              void* d_out, int out_size) {
    const float* x     = (const float*)d_in[0];
    const float* Dpap  = (const float*)d_in[1];
    const float* pa    = (const float*)d_in[2];
    const float* DecA  = (const float*)d_in[3];
    const float* A1buf = (const float*)d_in[4];
    const float* Wp    = (const float*)d_in[5];
    const float* bp    = (const float*)d_in[6];
    const float* Ws    = (const float*)d_in[7];
    const float* bs    = (const float*)d_in[8];
    const float* W1    = (const float*)d_in[9];
    const float* b1    = (const float*)d_in[10];
    const float* W2    = (const float*)d_in[11];
    const float* b2    = (const float*)d_in[12];
    const float* We    = (const float*)d_in[13];
    const float* be    = (const float*)d_in[14];
    const float* wt1   = (const float*)d_in[15];
    const float* wt2   = (const float*)d_in[16];
    const float* wtw1  = (const float*)d_in[17];
    const float* wtw2  = (const float*)d_in[18];
    const float* wtw11 = (const float*)d_in[19];
    const float* wtw21 = (const float*)d_in[20];
    const float* ws1   = (const float*)d_in[21];
    const float* ws2   = (const float*)d_in[22];
    const float* kca   = (const float*)d_in[23];
    const float* bn_g  = (const float*)d_in[24];
    const float* bn_b  = (const float*)d_in[25];
    float* out = (float*)d_out;

    cudaFuncSetAttribute(k5, cudaFuncAttributeMaxDynamicSharedMemorySize,
                         K5_SMEM_FLOATS * 4);

    kzero<<<400, 256>>>();
    k0<<<1, 256>>>(W2, Ws, b2, bs, Wp, bp, Dpap, pa, DecA, A1buf);
    k1<<<dim3(64, 32), 256>>>(x, Wp, bp);
    k2<<<64, 256>>>(wt1, wt2, wtw1, wtw2, wtw11, wtw21);
    k3<<<64, 256>>>();
    k4<<<64, 256>>>(W1, b1);
    k5<<<dim3(64, 32), 512, K5_SMEM_FLOATS * 4>>>(x);
    k6<<<64, 128>>>(ws1, ws2, We, be, kca);
    k7<<<dim3(64, 8), 256>>>(We, be);
    k8<<<1, 64>>>(bn_g, bn_b);
    k9<<<12800, 256>>>(x, out);
}

// round 4
// speedup vs baseline: 1.4102x; 1.0122x over previous
#include <cuda_runtime.h>
#include <math.h>

#define NN 64
#define CC 64
#define TT_ 128
#define VV 25

// ---------------- device scratch ----------------
__device__ float g_x1[NN*8*TT_*VV];
__device__ float g_xbar[NN*1600];
__device__ float g_A12[NN*150];
__device__ float g_att[NN*36];
__device__ float g_att2[NN*625];
__device__ float g_x1gcn[NN*8*TT_*6];
__device__ float g_ysm[NN*8*TT_*6];
__device__ float g_ybarS[NN*6];
__device__ float g_y1[NN*CC*TT_*VV];
__device__ float g_y1sum_nv[NN*VV];
__device__ float g_y1sum_nc[NN*CC];
__device__ float g_A12l[NN*150];
__device__ float g_gate[NN*CC];
__device__ float g_SY[CC], g_SYY[CC];
__device__ float g_scale[CC], g_shift[CC];
__device__ float g_WcombT[64*192];
__device__ float g_bcomb[192];
__device__ float g_WpMean[64], g_WsMean[64];
__device__ float g_bpMean[1], g_bsMean[1];
__device__ float g_nlp[864];
__device__ float g_nlA[15000];

__device__ const int c_joints[6] = {3, 20, 7, 11, 14, 18};

// ---------------- zero accumulators ----------------
__global__ void kzero() {
    int i = blockIdx.x * 256 + threadIdx.x;
    if (i < NN*1600) g_xbar[i] = 0.f;
    if (i < NN*CC) g_y1sum_nc[i] = 0.f;
    if (i < NN*VV) g_y1sum_nv[i] = 0.f;
    if (i < CC) { g_SY[i] = 0.f; g_SYY[i] = 0.f; }
}

// ---------------- K0: weight folding ----------------
__global__ void k0(const float* __restrict__ W2, const float* __restrict__ Ws,
                   const float* __restrict__ b2, const float* __restrict__ bs,
                   const float* __restrict__ Wp, const float* __restrict__ bp,
                   const float* __restrict__ Dpap, const float* __restrict__ pa,
                   const float* __restrict__ DecA, const float* __restrict__ A1buf) {
    int tid = threadIdx.x;
    for (int idx = tid; idx < 64*192; idx += 256) {
        int cj = idx / 192, r = idx % 192;
        float s = 0.f;
        for (int cm = 0; cm < 64; cm++) s += W2[r*64 + cm] * Ws[cm*64 + cj];
        g_WcombT[cj*192 + r] = s;
    }
    for (int r = tid; r < 192; r += 256) {
        float s = 0.f;
        for (int cm = 0; cm < 64; cm++) s += W2[r*64 + cm] * bs[cm];
        g_bcomb[r] = s + b2[r];
    }
    for (int ci = tid; ci < 64; ci += 256) {
        float s = 0.f;
        for (int o = 0; o < 8; o++) s += Wp[o*64 + ci];
        g_WpMean[ci] = s * (1.f/8.f);
        float s2 = 0.f;
        for (int c = 0; c < 64; c++) s2 += Ws[c*64 + ci];
        g_WsMean[ci] = s2 * (1.f/64.f);
    }
    if (tid == 0) {
        float s = 0.f; for (int o = 0; o < 8; o++) s += bp[o];
        g_bpMean[0] = s * (1.f/8.f);
        float s2 = 0.f; for (int c = 0; c < 64; c++) s2 += bs[c];
        g_bsMean[0] = s2 * (1.f/64.f);
    }
    for (int i = tid; i < 864; i += 256) g_nlp[i] = Dpap[i] + pa[i];
    for (int i = tid; i < 15000; i += 256) g_nlA[i] = A1buf[i] + DecA[i];
}

// ---------------- K1: x1 conv + xbar partial sums ----------------
__global__ void k1(const float* __restrict__ x, const float* __restrict__ Wp,
                   const float* __restrict__ bp) {
    __shared__ float xt[6400];   // [ci][100]
    __shared__ float Wps[512];
    __shared__ float bps[8];
    int n = blockIdx.x, t0 = blockIdx.y * 4, tid = threadIdx.x;
    const float4* x4 = reinterpret_cast<const float4*>(x);
    float4* xt4 = reinterpret_cast<float4*>(xt);
    int xbase4 = n*51200 + (t0/4)*25;
    for (int i = tid; i < 1600; i += 256) {
        int ci = i / 25, p4 = i % 25;
        xt4[ci*25 + p4] = x4[xbase4 + ci*800 + p4];
    }
    for (int i = tid; i < 512; i += 256) Wps[i] = Wp[i];
    if (tid < 8) bps[tid] = bp[tid];
    __syncthreads();
    for (int idx = tid; idx < 800; idx += 256) {
        int o = idx / 100, p = idx % 100;
        float acc = bps[o];
        #pragma unroll 16
        for (int ci = 0; ci < 64; ci++) acc += Wps[o*64 + ci] * xt[ci*100 + p];
        g_x1[((n*8 + o)*128 + t0)*25 + p] = acc;
    }
    for (int i = tid; i < 1600; i += 256) {
        int ci = i / 25, v = i % 25;
        float s = xt[ci*100 + v] + xt[ci*100 + 25 + v]
                + xt[ci*100 + 50 + v] + xt[ci*100 + 75 + v];
        atomicAdd(&g_xbar[n*1600 + i], s);
    }
}

// ---------------- K2: per-n stats + 3 softmaxes ----------------
__global__ void k2(const float* wt1p, const float* wt2p, const float* wtw1p,
                   const float* wtw2p, const float* wtw11p, const float* wtw21p) {
    __shared__ float xbs[1600];
    __shared__ float mb[25], xm2s[25], a1s[6], a2s[25], A12s[150], xms[6];
    int n = blockIdx.x, tid = threadIdx.x;
    for (int i = tid; i < 1600; i += 256) xbs[i] = g_xbar[n*1600 + i];
    __syncthreads();
    if (tid < 25) {
        float d1 = 0.f, d2 = 0.f;
        for (int ci = 0; ci < 64; ci++) {
            float xv = xbs[ci*25 + tid] * (1.f/128.f);
            d1 += xv * g_WpMean[ci];
            d2 += xv * g_WsMean[ci];
        }
        mb[tid] = d1 + g_bpMean[0];
        xm2s[tid] = d2 + g_bsMean[0];
    }
    __syncthreads();
    float wt1 = *wt1p, wt2 = *wt2p;
    if (tid < 25) a2s[tid] = fmaxf(wt2 * mb[tid], 0.f);
    if (tid < 6)  a1s[tid] = fmaxf(wt1 * mb[c_joints[tid]], 0.f);
    __syncthreads();
    if (tid < 25) {
        float e[6], mx = -1e30f;
        #pragma unroll
        for (int j = 0; j < 6; j++) { e[j] = a1s[j] * a2s[tid]; mx = fmaxf(mx, e[j]); }
        float sm = 0.f;
        #pragma unroll
        for (int j = 0; j < 6; j++) { e[j] = expf(e[j] - mx); sm += e[j]; }
        float inv = 1.f / sm;
        #pragma unroll
        for (int j = 0; j < 6; j++) {
            float v = e[j] * inv;
            A12s[j*25 + tid] = v;
            g_A12[n*150 + j*25 + tid] = v;
        }
    }
    __syncthreads();
    if (tid < 6) {
        float s = 0.f;
        for (int v = 0; v < 25; v++) s += mb[v] * A12s[tid*25 + v];
        xms[tid] = s;
    }
    __syncthreads();
    float wtw1 = *wtw1p, wtw2 = *wtw2p;
    if (tid < 6) {
        float r2w = fmaxf(wtw2 * xms[tid], 0.f);
        float e[6], mx = -1e30f;
        #pragma unroll
        for (int j = 0; j < 6; j++) { e[j] = fmaxf(wtw1 * xms[j], 0.f) * r2w; mx = fmaxf(mx, e[j]); }
        float sm = 0.f;
        #pragma unroll
        for (int j = 0; j < 6; j++) { e[j] = expf(e[j] - mx); sm += e[j]; }
        float inv = 1.f / sm;
        #pragma unroll
        for (int j = 0; j < 6; j++) g_att[n*36 + j*6 + tid] = e[j] * inv;
    }
    float wtw11 = *wtw11p, wtw21 = *wtw21p;
    if (tid < 25) {
        float r2w = fmaxf(wtw21 * xm2s[tid], 0.f);
        float e[25], mx = -1e30f;
        #pragma unroll
        for (int v = 0; v < 25; v++) { e[v] = fmaxf(wtw11 * xm2s[v], 0.f) * r2w; mx = fmaxf(mx, e[v]); }
        float sm = 0.f;
        #pragma unroll
        for (int v = 0; v < 25; v++) { e[v] = expf(e[v] - mx); sm += e[v]; }
        float inv = 1.f / sm;
        #pragma unroll
        for (int v = 0; v < 25; v++) g_att2[n*625 + v*25 + tid] = e[v] * inv;
    }
}

// ---------------- K3: x1_GCN = x1 @ A12^T ----------------
__global__ void k3() {
    __shared__ float A12s[150];
    int n = blockIdx.x, tid = threadIdx.x;
    for (int i = tid; i < 150; i += 256) A12s[i] = g_A12[n*150 + i];
    __syncthreads();
    for (int ot = tid; ot < 1024; ot += 256) {
        int o = ot >> 7, t = ot & 127;
        const float* xr = g_x1 + ((n*8 + o)*128 + t)*25;
        float xv[25];
        #pragma unroll
        for (int v = 0; v < 25; v++) xv[v] = xr[v];
        #pragma unroll
        for (int j = 0; j < 6; j++) {
            float s = 0.f;
            #pragma unroll
            for (int v = 0; v < 25; v++) s += xv[v] * A12s[j*25 + v];
            g_x1gcn[((n*8 + o)*128 + t)*6 + j] = s;
        }
    }
}

// ---------------- K4: small branch y + ybarS ----------------
__global__ void k4(const float* __restrict__ W1, const float* __restrict__ b1) {
    __shared__ float gcns[6144];
    __shared__ float W1s[192], b1s[24], Efb[864], yred[6];
    int n = blockIdx.x, tid = threadIdx.x;
    for (int i = tid; i < 6144; i += 256) gcns[i] = g_x1gcn[n*6144 + i];
    for (int i = tid; i < 192; i += 256) W1s[i] = W1[i];
    if (tid < 24) b1s[tid] = b1[tid];
    for (int i = tid; i < 864; i += 256) Efb[i] = 0.5f * g_att[n*36 + (i % 36)] + g_nlp[i];
    if (tid < 6) yred[tid] = 0.f;
    __syncthreads();
    float lsum[6] = {0.f, 0.f, 0.f, 0.f, 0.f, 0.f};
    for (int gt = tid; gt < 1024; gt += 256) {
        int g = gt >> 7, t = gt & 127;
        float mloc[3][6];
        #pragma unroll
        for (int k = 0; k < 3; k++) {
            const float* wrow = &W1s[(k*8 + g)*8];
            float bb = b1s[k*8 + g];
            #pragma unroll
            for (int j = 0; j < 6; j++) {
                float s = bb;
                #pragma unroll
                for (int o = 0; o < 8; o++) s += gcns[(o*128 + t)*6 + j] * wrow[o];
                mloc[k][j] = s;
            }
        }
        #pragma unroll
        for (int w = 0; w < 6; w++) {
            float s = 0.f;
            #pragma unroll
            for (int k = 0; k < 3; k++)
                #pragma unroll
                for (int j = 0; j < 6; j++)
                    s += mloc[k][j] * Efb[((k*8 + g)*6 + j)*6 + w];
            g_ysm[(n*8 + g)*768 + t*6 + w] = s;
            lsum[w] += s;
        }
    }
    #pragma unroll
    for (int w = 0; w < 6; w++) atomicAdd(&yred[w], lsum[w]);
    __syncthreads();
    if (tid < 6) g_ybarS[n*6 + tid] = yred[tid] * (1.f/1024.f);
}

// ---------------- K5: heavy y1 kernel (t-tile=4, conflict-free) ----------------
// smem: Wcs[12288] | Ds[16800] | m2s[192*105] | xt[6400] | red[128] | bcs[192]
#define K5_SMEM_FLOATS (12288 + 16800 + 20160 + 6400 + 128 + 192)
__global__ void __launch_bounds__(512, 1) k5(const float* __restrict__ x) {
    extern __shared__ float sm[];
    float* Wcs = sm;
    float* Ds  = Wcs + 12288;
    float* m2s = Ds + 16800;          // stride 105 per row
    float* xt  = m2s + 20160;
    float* red = xt + 6400;
    float* bcs = red + 128;
    int n = blockIdx.x, t0 = blockIdx.y * 4, tid = threadIdx.x;
    if (tid < 128) red[tid] = 0.f;
    if (tid < 192) bcs[tid] = g_bcomb[tid];
    {
        const float4* Wg4 = reinterpret_cast<const float4*>(g_WcombT);
        float4* Ws4 = reinterpret_cast<float4*>(Wcs);
        for (int i = tid; i < 3072; i += 512) Ws4[i] = Wg4[i];
        const float4* x4 = reinterpret_cast<const float4*>(x);
        float4* xt4 = reinterpret_cast<float4*>(xt);
        int xbase4 = n*51200 + (t0/4)*25;
        for (int i = tid; i < 1600; i += 512) {
            int ci = i / 25, p4 = i % 25;
            xt4[ci*25 + p4] = x4[xbase4 + ci*800 + p4];
        }
    }
    const float* at2 = g_att2 + n*625;
    for (int i = tid; i < 16800; i += 512) {
        int g = i / 2100, r = i % 2100, kv = r / 28, w = r % 28;
        float val = 0.f;
        if (w < 25) {
            int k = kv / 25, v = kv % 25;
            val = g_nlA[((k*8 + g)*25 + v)*25 + w] + 0.5f * at2[v*25 + w];
        }
        Ds[i] = val;
    }
    __syncthreads();
    // phase A: m2[r][p], tile = 8r x 4p; pp fastest for conflict-free xt reads
    {
        const float4* W4 = reinterpret_cast<const float4*>(Wcs);
        const float4* xt4 = reinterpret_cast<const float4*>(xt);
        for (int tile = tid; tile < 600; tile += 512) {
            int pp = tile % 25, rq = tile / 25;
            float acc[8][4];
            #pragma unroll
            for (int i = 0; i < 8; i++)
                #pragma unroll
                for (int j = 0; j < 4; j++) acc[i][j] = 0.f;
            #pragma unroll 8
            for (int ci = 0; ci < 64; ci++) {
                float4 w0 = W4[ci*48 + rq*2];
                float4 w1 = W4[ci*48 + rq*2 + 1];
                float4 xv = xt4[ci*25 + pp];
                float xa[4] = {xv.x, xv.y, xv.z, xv.w};
                float wa[8] = {w0.x, w0.y, w0.z, w0.w, w1.x, w1.y, w1.z, w1.w};
                #pragma unroll
                for (int i = 0; i < 8; i++)
                    #pragma unroll
                    for (int j = 0; j < 4; j++) acc[i][j] += wa[i]*xa[j];
            }
            int r0 = rq * 8, p0 = pp * 4;
            #pragma unroll
            for (int i = 0; i < 8; i++) {
                float bb = bcs[r0 + i];
                #pragma unroll
                for (int j = 0; j < 4; j++) {
                    int p = p0 + j, tt = p / 25, v = p % 25;
                    m2s[(r0 + i)*105 + tt*26 + v] = acc[i][j] + bb;
                }
            }
        }
    }
    __syncthreads();
    // phase B: 448 tiles, each 1c x 4t x 4w; results staged into xt
    if (tid < 448) {
        int c = tid & 63, wq = tid >> 6, w0 = wq * 4, g = c & 7;
        float acc[4][4];
        #pragma unroll
        for (int tt = 0; tt < 4; tt++)
            #pragma unroll
            for (int j = 0; j < 4; j++) acc[tt][j] = 0.f;
        #pragma unroll
        for (int k = 0; k < 3; k++) {
            const float* mrow = &m2s[(k*64 + c)*105];
            const float4* dr = reinterpret_cast<const float4*>(&Ds[(g*75 + k*25)*28 + w0]);
            #pragma unroll 5
            for (int v = 0; v < 25; v++) {
                float4 d = dr[v*7];
                float da[4] = {d.x, d.y, d.z, d.w};
                float m0 = mrow[v], m1 = mrow[26 + v], m2v = mrow[52 + v], m3 = mrow[78 + v];
                #pragma unroll
                for (int j = 0; j < 4; j++) {
                    acc[0][j] += m0 * da[j];
                    acc[1][j] += m1 * da[j];
                    acc[2][j] += m2v * da[j];
                    acc[3][j] += m3 * da[j];
                }
            }
        }
        float csum = 0.f;
        #pragma unroll
        for (int j = 0; j < 4; j++) {
            int w = w0 + j;
            if (w < 25) {
                float ws = 0.f;
                #pragma unroll
                for (int tt = 0; tt < 4; tt++) {
                    xt[c*100 + tt*25 + w] = acc[tt][j];
                    ws += acc[tt][j];
                }
                atomicAdd(&red[w], ws);
                csum += ws;
            }
        }
        atomicAdd(&red[32 + c], csum);
    }
    __syncthreads();
    // coalesced writeback of staged y1 tile
    {
        const float4* xt4 = reinterpret_cast<const float4*>(xt);
        float4* y14 = reinterpret_cast<float4*>(g_y1);
        int base4 = (n*204800 + t0*25) / 4;
        for (int i = tid; i < 1600; i += 512) {
            int c = i / 25, q4 = i % 25;
            y14[base4 + c*800 + q4] = xt4[c*25 + q4];
        }
    }
    if (tid < 25) atomicAdd(&g_y1sum_nv[n*25 + tid], red[tid]);
    if (tid >= 32 && tid < 96) atomicAdd(&g_y1sum_nc[n*64 + tid - 32], red[tid]);
}

// ---------------- K6: A12l + channel gate ----------------
__global__ void k6(const float* ws1p, const float* ws2p,
                   const float* __restrict__ We, const float* __restrict__ be,
                   const float* __restrict__ kca) {
    __shared__ float a1ls[6], A12ls[150], ytsum[48], Asum[6], Ssum[8], qs[64];
    int n = blockIdx.x, tid = threadIdx.x;
    if (tid < 6) a1ls[tid] = fmaxf((*ws1p) * g_ybarS[n*6 + tid], 0.f);
    __syncthreads();
    if (tid < 25) {
        float a2 = fmaxf((*ws2p) * g_y1sum_nv[n*25 + tid] * (1.f/8192.f), 0.f);
        float e[6], mx = -1e30f;
        #pragma unroll
        for (int j = 0; j < 6; j++) { e[j] = a1ls[j] * a2; mx = fmaxf(mx, e[j]); }
        float s = 0.f;
        #pragma unroll
        for (int j = 0; j < 6; j++) { e[j] = expf(e[j] - mx); s += e[j]; }
        float inv = 1.f / s;
        #pragma unroll
        for (int j = 0; j < 6; j++) {
            float v = e[j] * inv;
            A12ls[j*25 + tid] = v;
            g_A12l[n*150 + j*25 + tid] = v;
        }
    }
    for (int i = tid; i < 48; i += 128) {
        int o = i / 6, j = i % 6;
        float s = 0.f;
        for (int t = 0; t < 128; t++) s += g_ysm[(n*8 + o)*768 + t*6 + j];
        ytsum[i] = s;
    }
    __syncthreads();
    if (tid < 6) {
        float s = 0.f;
        for (int v = 0; v < 25; v++) s += A12ls[tid*25 + v];
        Asum[tid] = s;
    }
    __syncthreads();
    if (tid < 8) {
        float s = 0.f;
        #pragma unroll
        for (int j = 0; j < 6; j++) s += ytsum[tid*6 + j] * Asum[j];
        Ssum[tid] = s;
    }
    __syncthreads();
    if (tid < 64) {
        float yls = 3200.f * be[tid];
        #pragma unroll
        for (int o = 0; o < 8; o++) yls += We[tid*8 + o] * Ssum[o];
        qs[tid] = (g_y1sum_nc[n*64 + tid] + 0.5f * yls) * (1.f/3200.f);
    }
    __syncthreads();
    if (tid < 64) {
        float qm = (tid > 0) ? qs[tid-1] : 0.f;
        float q0 = qs[tid];
        float qp1 = (tid < 63) ? qs[tid+1] : 0.f;
        float qc = kca[0]*qm + kca[1]*q0 + kca[2]*qp1;
        g_gate[n*64 + tid] = 1.f + 1.f/(1.f + expf(-qc));
    }
}

// ---------------- K7: Y = (0.5*yl + y1)*gate, BN stats (coalesced) ----------------
__global__ void k7(const float* __restrict__ We, const float* __restrict__ be) {
    __shared__ float A12ls[150], Wes[512], bes[64], gates[64], ytile[768], zs[3200];
    int n = blockIdx.x, t0 = blockIdx.y * 16, tid = threadIdx.x;
    for (int i = tid; i < 150; i += 256) A12ls[i] = g_A12l[n*150 + i];
    for (int i = tid; i < 512; i += 256) Wes[i] = We[i];
    if (tid < 64) { bes[tid] = be[tid]; gates[tid] = g_gate[n*64 + tid]; }
    for (int i = tid; i < 768; i += 256) {
        int o = i / 96, r = i % 96, t = r / 6, j = r % 6;
        ytile[i] = g_ysm[(n*8 + o)*768 + (t0 + t)*6 + j];
    }
    __syncthreads();
    for (int i = tid; i < 3200; i += 256) {
        int o = i / 400, r = i % 400, t = r / 25, v = r % 25;
        float s = 0.f;
        #pragma unroll
        for (int j = 0; j < 6; j++) s += ytile[o*96 + t*6 + j] * A12ls[j*25 + v];
        zs[i] = s;
    }
    __syncthreads();
    int warp = tid >> 5, lane = tid & 31;
    for (int cc = warp; cc < 64; cc += 8) {
        float wrow[8];
        #pragma unroll
        for (int o = 0; o < 8; o++) wrow[o] = Wes[cc*8 + o];
        float bc = bes[cc], gt = gates[cc];
        float lsy = 0.f, lsyy = 0.f;
        int base = ((n*64 + cc)*128 + t0)*25;
        for (int i = lane; i < 400; i += 32) {
            float yl = bc;
            #pragma unroll
            for (int o = 0; o < 8; o++) yl += wrow[o] * zs[o*400 + i];
            float Y = 0.5f*yl + g_y1[base + i];
            float Yg = Y * gt;
            g_y1[base + i] = Yg;
            lsy += Yg;
            lsyy += Yg * Yg;
        }
        #pragma unroll
        for (int off = 16; off > 0; off >>= 1) {
            lsy  += __shfl_down_sync(0xffffffffu, lsy, off);
            lsyy += __shfl_down_sync(0xffffffffu, lsyy, off);
        }
        if (lane == 0) {
            atomicAdd(&g_SY[cc], lsy);
            atomicAdd(&g_SYY[cc], lsyy);
        }
    }
}

// ---------------- K8: BN finalize ----------------
__global__ void k8(const float* __restrict__ bn_g, const float* __restrict__ bn_b) {
    int c = threadIdx.x;
    if (c < 64) {
        const float cnt = 204800.f;
        float mu = g_SY[c] / cnt;
        float var = g_SYY[c] / cnt - mu*mu;
        float sc = bn_g[c] * rsqrtf(var + 1e-5f);
        g_scale[c] = sc;
        g_shift[c] = bn_b[c] - mu*sc;
    }
}

// ---------------- K9: out = relu(BN(Yg) + x) ----------------
__global__ void k9(const float* __restrict__ x, float* __restrict__ out) {
    int i = blockIdx.x * 256 + threadIdx.x;
    if (i >= 3276800) return;
    int c = (i / 800) & 63;
    float4 yv = reinterpret_cast<const float4*>(g_y1)[i];
    float4 xv = reinterpret_cast<const float4*>(x)[i];
    float sc = g_scale[c], sh = g_shift[c];
    float4 o;
    o.x = fmaxf(yv.x*sc + sh + xv.x, 0.f);
    o.y = fmaxf(yv.y*sc + sh + xv.y, 0.f);
    o.z = fmaxf(yv.z*sc + sh + xv.z, 0.f);
    o.w = fmaxf(yv.w*sc + sh + xv.w, 0.f);
    reinterpret_cast<float4*>(out)[i] = o;
}

// ---------------- launch ----------------
extern "C" void kernel_launch(void* const* d_in, const int* in_sizes, int n_in,
                              void* d_out, int out_size) {
    const float* x     = (const float*)d_in[0];
    const float* Dpap  = (const float*)d_in[1];
    const float* pa    = (const float*)d_in[2];
    const float* DecA  = (const float*)d_in[3];
    const float* A1buf = (const float*)d_in[4];
    const float* Wp    = (const float*)d_in[5];
    const float* bp    = (const float*)d_in[6];
    const float* Ws    = (const float*)d_in[7];
    const float* bs    = (const float*)d_in[8];
    const float* W1    = (const float*)d_in[9];
    const float* b1    = (const float*)d_in[10];
    const float* W2    = (const float*)d_in[11];
    const float* b2    = (const float*)d_in[12];
    const float* We    = (const float*)d_in[13];
    const float* be    = (const float*)d_in[14];
    const float* wt1   = (const float*)d_in[15];
    const float* wt2   = (const float*)d_in[16];
    const float* wtw1  = (const float*)d_in[17];
    const float* wtw2  = (const float*)d_in[18];
    const float* wtw11 = (const float*)d_in[19];
    const float* wtw21 = (const float*)d_in[20];
    const float* ws1   = (const float*)d_in[21];
    const float* ws2   = (const float*)d_in[22];
    const float* kca   = (const float*)d_in[23];
    const float* bn_g  = (const float*)d_in[24];
    const float* bn_b  = (const float*)d_in[25];
    float* out = (float*)d_out;

    cudaFuncSetAttribute(k5, cudaFuncAttributeMaxDynamicSharedMemorySize,
                         K5_SMEM_FLOATS * 4);

    kzero<<<400, 256>>>();
    k0<<<1, 256>>>(W2, Ws, b2, bs, Wp, bp, Dpap, pa, DecA, A1buf);
    k1<<<dim3(64, 32), 256>>>(x, Wp, bp);
    k2<<<64, 256>>>(wt1, wt2, wtw1, wtw2, wtw11, wtw21);
    k3<<<64, 256>>>();
    k4<<<64, 256>>>(W1, b1);
    k5<<<dim3(64, 32), 512, K5_SMEM_FLOATS * 4>>>(x);
    k6<<<64, 128>>>(ws1, ws2, We, be, kca);
    k7<<<dim3(64, 8), 256>>>(We, be);
    k8<<<1, 64>>>(bn_g, bn_b);
    k9<<<12800, 256>>>(x, out);
}

// round 5
// speedup vs baseline: 1.4153x; 1.0036x over previous
#include <cuda_runtime.h>
#include <math.h>

#define NN 64
#define CC 64
#define TT_ 128
#define VV 25

// ---------------- device scratch ----------------
__device__ float g_x1[NN*8*TT_*VV];
__device__ float g_xbar[NN*1600];
__device__ float g_A12[NN*150];
__device__ float g_att[NN*36];
__device__ float g_att2[NN*625];
__device__ float g_x1gcn[NN*8*TT_*6];
__device__ float g_ysm[NN*8*TT_*6];
__device__ float g_ybarS[NN*6];
__device__ float g_y1[NN*CC*TT_*VV];
__device__ float g_y1sum_nv[NN*VV];
__device__ float g_y1sum_nc[NN*CC];
__device__ float g_A12l[NN*150];
__device__ float g_gate[NN*CC];
__device__ float g_SY[CC], g_SYY[CC];
__device__ float g_WcombT[64*192];
__device__ float g_bcomb[192];
__device__ float g_WpMean[64], g_WsMean[64];
__device__ float g_bpMean[1], g_bsMean[1];
__device__ float g_nlp[864];
__device__ float g_nlA[15000];

__device__ const int c_joints[6] = {3, 20, 7, 11, 14, 18};

// ---------------- K0z: zero accumulators + weight folding (block 0) ----------------
__global__ void k0z(const float* __restrict__ W2, const float* __restrict__ Ws,
                    const float* __restrict__ b2, const float* __restrict__ bs,
                    const float* __restrict__ Wp, const float* __restrict__ bp,
                    const float* __restrict__ Dpap, const float* __restrict__ pa,
                    const float* __restrict__ DecA, const float* __restrict__ A1buf) {
    int gi = blockIdx.x * 256 + threadIdx.x;
    if (gi < NN*1600) g_xbar[gi] = 0.f;
    if (gi < NN*CC) g_y1sum_nc[gi] = 0.f;
    if (gi < NN*VV) g_y1sum_nv[gi] = 0.f;
    if (gi < CC) { g_SY[gi] = 0.f; g_SYY[gi] = 0.f; }
    if (blockIdx.x != 0) return;
    int tid = threadIdx.x;
    for (int idx = tid; idx < 64*192; idx += 256) {
        int cj = idx / 192, r = idx % 192;
        float s = 0.f;
        for (int cm = 0; cm < 64; cm++) s += W2[r*64 + cm] * Ws[cm*64 + cj];
        g_WcombT[cj*192 + r] = s;
    }
    for (int r = tid; r < 192; r += 256) {
        float s = 0.f;
        for (int cm = 0; cm < 64; cm++) s += W2[r*64 + cm] * bs[cm];
        g_bcomb[r] = s + b2[r];
    }
    for (int ci = tid; ci < 64; ci += 256) {
        float s = 0.f;
        for (int o = 0; o < 8; o++) s += Wp[o*64 + ci];
        g_WpMean[ci] = s * (1.f/8.f);
        float s2 = 0.f;
        for (int c = 0; c < 64; c++) s2 += Ws[c*64 + ci];
        g_WsMean[ci] = s2 * (1.f/64.f);
    }
    if (tid == 0) {
        float s = 0.f; for (int o = 0; o < 8; o++) s += bp[o];
        g_bpMean[0] = s * (1.f/8.f);
        float s2 = 0.f; for (int c = 0; c < 64; c++) s2 += bs[c];
        g_bsMean[0] = s2 * (1.f/64.f);
    }
    for (int i = tid; i < 864; i += 256) g_nlp[i] = Dpap[i] + pa[i];
    for (int i = tid; i < 15000; i += 256) g_nlA[i] = A1buf[i] + DecA[i];
}

// ---------------- K1: x1 conv + xbar partial sums (t-tile 8) ----------------
__global__ void __launch_bounds__(512) k1(const float* __restrict__ x,
                                          const float* __restrict__ Wp,
                                          const float* __restrict__ bp) {
    __shared__ float xt[12800];   // [ci][200]
    __shared__ float Wps[512];
    __shared__ float bps[8];
    int n = blockIdx.x, t0 = blockIdx.y * 8, tid = threadIdx.x;
    const float4* x4 = reinterpret_cast<const float4*>(x);
    float4* xt4 = reinterpret_cast<float4*>(xt);
    int xbase4 = n*51200 + (t0*25)/4;
    for (int i = tid; i < 3200; i += 512) {
        int ci = i / 50, p4 = i % 50;
        xt4[ci*50 + p4] = x4[xbase4 + ci*800 + p4];
    }
    for (int i = tid; i < 512; i += 512) Wps[i] = Wp[i];
    if (tid < 8) bps[tid] = bp[tid];
    __syncthreads();
    for (int idx = tid; idx < 1600; idx += 512) {
        int o = idx / 200, p = idx % 200;
        float acc = bps[o];
        #pragma unroll 16
        for (int ci = 0; ci < 64; ci++) acc += Wps[o*64 + ci] * xt[ci*200 + p];
        g_x1[((n*8 + o)*128 + t0)*25 + p] = acc;
    }
    for (int i = tid; i < 1600; i += 512) {
        int ci = i / 25, v = i % 25;
        float s = 0.f;
        #pragma unroll
        for (int tt = 0; tt < 8; tt++) s += xt[ci*200 + tt*25 + v];
        atomicAdd(&g_xbar[n*1600 + i], s);
    }
}

// ---------------- K2: per-n stats + 3 softmaxes + x1_GCN ----------------
__global__ void k2(const float* wt1p, const float* wt2p, const float* wtw1p,
                   const float* wtw2p, const float* wtw11p, const float* wtw21p) {
    __shared__ float xbs[1600];
    __shared__ float mb[25], xm2s[25], a1s[6], a2s[25], A12s[150], xms[6];
    int n = blockIdx.x, tid = threadIdx.x;
    for (int i = tid; i < 1600; i += 256) xbs[i] = g_xbar[n*1600 + i];
    __syncthreads();
    if (tid < 25) {
        float d1 = 0.f, d2 = 0.f;
        for (int ci = 0; ci < 64; ci++) {
            float xv = xbs[ci*25 + tid] * (1.f/128.f);
            d1 += xv * g_WpMean[ci];
            d2 += xv * g_WsMean[ci];
        }
        mb[tid] = d1 + g_bpMean[0];
        xm2s[tid] = d2 + g_bsMean[0];
    }
    __syncthreads();
    float wt1 = *wt1p, wt2 = *wt2p;
    if (tid < 25) a2s[tid] = fmaxf(wt2 * mb[tid], 0.f);
    if (tid < 6)  a1s[tid] = fmaxf(wt1 * mb[c_joints[tid]], 0.f);
    __syncthreads();
    if (tid < 25) {
        float e[6], mx = -1e30f;
        #pragma unroll
        for (int j = 0; j < 6; j++) { e[j] = a1s[j] * a2s[tid]; mx = fmaxf(mx, e[j]); }
        float sm = 0.f;
        #pragma unroll
        for (int j = 0; j < 6; j++) { e[j] = expf(e[j] - mx); sm += e[j]; }
        float inv = 1.f / sm;
        #pragma unroll
        for (int j = 0; j < 6; j++) {
            float v = e[j] * inv;
            A12s[j*25 + tid] = v;
            g_A12[n*150 + j*25 + tid] = v;
        }
    }
    __syncthreads();
    if (tid < 6) {
        float s = 0.f;
        for (int v = 0; v < 25; v++) s += mb[v] * A12s[tid*25 + v];
        xms[tid] = s;
    }
    __syncthreads();
    float wtw1 = *wtw1p, wtw2 = *wtw2p;
    if (tid < 6) {
        float r2w = fmaxf(wtw2 * xms[tid], 0.f);
        float e[6], mx = -1e30f;
        #pragma unroll
        for (int j = 0; j < 6; j++) { e[j] = fmaxf(wtw1 * xms[j], 0.f) * r2w; mx = fmaxf(mx, e[j]); }
        float sm = 0.f;
        #pragma unroll
        for (int j = 0; j < 6; j++) { e[j] = expf(e[j] - mx); sm += e[j]; }
        float inv = 1.f / sm;
        #pragma unroll
        for (int j = 0; j < 6; j++) g_att[n*36 + j*6 + tid] = e[j] * inv;
    }
    float wtw11 = *wtw11p, wtw21 = *wtw21p;
    if (tid < 25) {
        float r2w = fmaxf(wtw21 * xm2s[tid], 0.f);
        float e[25], mx = -1e30f;
        #pragma unroll
        for (int v = 0; v < 25; v++) { e[v] = fmaxf(wtw11 * xm2s[v], 0.f) * r2w; mx = fmaxf(mx, e[v]); }
        float sm = 0.f;
        #pragma unroll
        for (int v = 0; v < 25; v++) { e[v] = expf(e[v] - mx); sm += e[v]; }
        float inv = 1.f / sm;
        #pragma unroll
        for (int v = 0; v < 25; v++) g_att2[n*625 + v*25 + tid] = e[v] * inv;
    }
    __syncthreads();
    // fused x1_GCN = x1 @ A12^T
    for (int ot = tid; ot < 1024; ot += 256) {
        int o = ot >> 7, t = ot & 127;
        const float* xr = g_x1 + ((n*8 + o)*128 + t)*25;
        float xv[25];
        #pragma unroll
        for (int v = 0; v < 25; v++) xv[v] = xr[v];
        #pragma unroll
        for (int j = 0; j < 6; j++) {
            float s = 0.f;
            #pragma unroll
            for (int v = 0; v < 25; v++) s += xv[v] * A12s[j*25 + v];
            g_x1gcn[((n*8 + o)*128 + t)*6 + j] = s;
        }
    }
}

// ---------------- K5: heavy y1 kernel (balanced 12r x 4p phase A) ----------------
// smem: Wcs[12288] | Ds[16800] | m2s[192*105] | xt[6400] | red[128] | bcs[192]
#define K5_SMEM_FLOATS (12288 + 16800 + 20160 + 6400 + 128 + 192)
__global__ void __launch_bounds__(512, 1) k5(const float* __restrict__ x) {
    extern __shared__ float sm[];
    float* Wcs = sm;
    float* Ds  = Wcs + 12288;
    float* m2s = Ds + 16800;          // stride 105 per row
    float* xt  = m2s + 20160;
    float* red = xt + 6400;
    float* bcs = red + 128;
    int n = blockIdx.x, t0 = blockIdx.y * 4, tid = threadIdx.x;
    if (tid < 128) red[tid] = 0.f;
    if (tid < 192) bcs[tid] = g_bcomb[tid];
    {
        const float4* Wg4 = reinterpret_cast<const float4*>(g_WcombT);
        float4* Ws4 = reinterpret_cast<float4*>(Wcs);
        for (int i = tid; i < 3072; i += 512) Ws4[i] = Wg4[i];
        const float4* x4 = reinterpret_cast<const float4*>(x);
        float4* xt4 = reinterpret_cast<float4*>(xt);
        int xbase4 = n*51200 + (t0/4)*25;
        for (int i = tid; i < 1600; i += 512) {
            int ci = i / 25, p4 = i % 25;
            xt4[ci*25 + p4] = x4[xbase4 + ci*800 + p4];
        }
    }
    const float* at2 = g_att2 + n*625;
    for (int i = tid; i < 16800; i += 512) {
        int g = i / 2100, r = i % 2100, kv = r / 28, w = r % 28;
        float val = 0.f;
        if (w < 25) {
            int k = kv / 25, v = kv % 25;
            val = g_nlA[((k*8 + g)*25 + v)*25 + w] + 0.5f * at2[v*25 + w];
        }
        Ds[i] = val;
    }
    __syncthreads();
    // phase A: m2[r][p], 400 tiles of 12r x 4p, one per thread
    if (tid < 400) {
        const float4* W4 = reinterpret_cast<const float4*>(Wcs);
        const float4* xt4 = reinterpret_cast<const float4*>(xt);
        int pp = tid % 25, rq = tid / 25;
        float acc[12][4];
        #pragma unroll
        for (int i = 0; i < 12; i++)
            #pragma unroll
            for (int j = 0; j < 4; j++) acc[i][j] = 0.f;
        #pragma unroll 8
        for (int ci = 0; ci < 64; ci++) {
            float4 w0 = W4[ci*48 + rq*3];
            float4 w1 = W4[ci*48 + rq*3 + 1];
            float4 w2 = W4[ci*48 + rq*3 + 2];
            float4 xv = xt4[ci*25 + pp];
            float xa[4] = {xv.x, xv.y, xv.z, xv.w};
            float wa[12] = {w0.x, w0.y, w0.z, w0.w, w1.x, w1.y, w1.z, w1.w,
                            w2.x, w2.y, w2.z, w2.w};
            #pragma unroll
            for (int i = 0; i < 12; i++)
                #pragma unroll
                for (int j = 0; j < 4; j++) acc[i][j] += wa[i]*xa[j];
        }
        int r0 = rq * 12, p0 = pp * 4;
        #pragma unroll
        for (int i = 0; i < 12; i++) {
            float bb = bcs[r0 + i];
            #pragma unroll
            for (int j = 0; j < 4; j++) {
                int p = p0 + j, tt = p / 25, v = p % 25;
                m2s[(r0 + i)*105 + tt*26 + v] = acc[i][j] + bb;
            }
        }
    }
    __syncthreads();
    // phase B: 448 tiles, each 1c x 4t x 4w; results staged into xt
    if (tid < 448) {
        int c = tid & 63, wq = tid >> 6, w0 = wq * 4, g = c & 7;
        float acc[4][4];
        #pragma unroll
        for (int tt = 0; tt < 4; tt++)
            #pragma unroll
            for (int j = 0; j < 4; j++) acc[tt][j] = 0.f;
        #pragma unroll
        for (int k = 0; k < 3; k++) {
            const float* mrow = &m2s[(k*64 + c)*105];
            const float4* dr = reinterpret_cast<const float4*>(&Ds[(g*75 + k*25)*28 + w0]);
            #pragma unroll 5
            for (int v = 0; v < 25; v++) {
                float4 d = dr[v*7];
                float da[4] = {d.x, d.y, d.z, d.w};
                float m0 = mrow[v], m1 = mrow[26 + v], m2v = mrow[52 + v], m3 = mrow[78 + v];
                #pragma unroll
                for (int j = 0; j < 4; j++) {
                    acc[0][j] += m0 * da[j];
                    acc[1][j] += m1 * da[j];
                    acc[2][j] += m2v * da[j];
                    acc[3][j] += m3 * da[j];
                }
            }
        }
        float csum = 0.f;
        #pragma unroll
        for (int j = 0; j < 4; j++) {
            int w = w0 + j;
            if (w < 25) {
                float ws = 0.f;
                #pragma unroll
                for (int tt = 0; tt < 4; tt++) {
                    xt[c*100 + tt*25 + w] = acc[tt][j];
                    ws += acc[tt][j];
                }
                atomicAdd(&red[w], ws);
                csum += ws;
            }
        }
        atomicAdd(&red[32 + c], csum);
    }
    __syncthreads();
    {
        const float4* xt4 = reinterpret_cast<const float4*>(xt);
        float4* y14 = reinterpret_cast<float4*>(g_y1);
        int base4 = (n*204800 + t0*25) / 4;
        for (int i = tid; i < 1600; i += 512) {
            int c = i / 25, q4 = i % 25;
            y14[base4 + c*800 + q4] = xt4[c*25 + q4];
        }
    }
    if (tid < 25) atomicAdd(&g_y1sum_nv[n*25 + tid], red[tid]);
    if (tid >= 32 && tid < 96) atomicAdd(&g_y1sum_nc[n*64 + tid - 32], red[tid]);
}

// ---------------- K4: small branch y + ybarS ----------------
__global__ void k4(const float* __restrict__ W1, const float* __restrict__ b1) {
    __shared__ float gcns[6144];
    __shared__ float W1s[192], b1s[24], Efb[864], yred[6];
    int n = blockIdx.x, tid = threadIdx.x;
    for (int i = tid; i < 6144; i += 256) gcns[i] = g_x1gcn[n*6144 + i];
    for (int i = tid; i < 192; i += 256) W1s[i] = W1[i];
    if (tid < 24) b1s[tid] = b1[tid];
    for (int i = tid; i < 864; i += 256) Efb[i] = 0.5f * g_att[n*36 + (i % 36)] + g_nlp[i];
    if (tid < 6) yred[tid] = 0.f;
    __syncthreads();
    float lsum[6] = {0.f, 0.f, 0.f, 0.f, 0.f, 0.f};
    for (int gt = tid; gt < 1024; gt += 256) {
        int g = gt >> 7, t = gt & 127;
        float mloc[3][6];
        #pragma unroll
        for (int k = 0; k < 3; k++) {
            const float* wrow = &W1s[(k*8 + g)*8];
            float bb = b1s[k*8 + g];
            #pragma unroll
            for (int j = 0; j < 6; j++) {
                float s = bb;
                #pragma unroll
                for (int o = 0; o < 8; o++) s += gcns[(o*128 + t)*6 + j] * wrow[o];
                mloc[k][j] = s;
            }
        }
        #pragma unroll
        for (int w = 0; w < 6; w++) {
            float s = 0.f;
            #pragma unroll
            for (int k = 0; k < 3; k++)
                #pragma unroll
                for (int j = 0; j < 6; j++)
                    s += mloc[k][j] * Efb[((k*8 + g)*6 + j)*6 + w];
            g_ysm[(n*8 + g)*768 + t*6 + w] = s;
            lsum[w] += s;
        }
    }
    #pragma unroll
    for (int w = 0; w < 6; w++) atomicAdd(&yred[w], lsum[w]);
    __syncthreads();
    if (tid < 6) g_ybarS[n*6 + tid] = yred[tid] * (1.f/1024.f);
}

// ---------------- K6: A12l + channel gate ----------------
__global__ void k6(const float* ws1p, const float* ws2p,
                   const float* __restrict__ We, const float* __restrict__ be,
                   const float* __restrict__ kca) {
    __shared__ float a1ls[6], A12ls[150], ytsum[48], Asum[6], Ssum[8], qs[64];
    int n = blockIdx.x, tid = threadIdx.x;
    if (tid < 6) a1ls[tid] = fmaxf((*ws1p) * g_ybarS[n*6 + tid], 0.f);
    __syncthreads();
    if (tid < 25) {
        float a2 = fmaxf((*ws2p) * g_y1sum_nv[n*25 + tid] * (1.f/8192.f), 0.f);
        float e[6], mx = -1e30f;
        #pragma unroll
        for (int j = 0; j < 6; j++) { e[j] = a1ls[j] * a2; mx = fmaxf(mx, e[j]); }
        float s = 0.f;
        #pragma unroll
        for (int j = 0; j < 6; j++) { e[j] = expf(e[j] - mx); s += e[j]; }
        float inv = 1.f / s;
        #pragma unroll
        for (int j = 0; j < 6; j++) {
            float v = e[j] * inv;
            A12ls[j*25 + tid] = v;
            g_A12l[n*150 + j*25 + tid] = v;
        }
    }
    for (int i = tid; i < 48; i += 128) {
        int o = i / 6, j = i % 6;
        float s = 0.f;
        for (int t = 0; t < 128; t++) s += g_ysm[(n*8 + o)*768 + t*6 + j];
        ytsum[i] = s;
    }
    __syncthreads();
    if (tid < 6) {
        float s = 0.f;
        for (int v = 0; v < 25; v++) s += A12ls[tid*25 + v];
        Asum[tid] = s;
    }
    __syncthreads();
    if (tid < 8) {
        float s = 0.f;
        #pragma unroll
        for (int j = 0; j < 6; j++) s += ytsum[tid*6 + j] * Asum[j];
        Ssum[tid] = s;
    }
    __syncthreads();
    if (tid < 64) {
        float yls = 3200.f * be[tid];
        #pragma unroll
        for (int o = 0; o < 8; o++) yls += We[tid*8 + o] * Ssum[o];
        qs[tid] = (g_y1sum_nc[n*64 + tid] + 0.5f * yls) * (1.f/3200.f);
    }
    __syncthreads();
    if (tid < 64) {
        float qm = (tid > 0) ? qs[tid-1] : 0.f;
        float q0 = qs[tid];
        float qp1 = (tid < 63) ? qs[tid+1] : 0.f;
        float qc = kca[0]*qm + kca[1]*q0 + kca[2]*qp1;
        g_gate[n*64 + tid] = 1.f + 1.f/(1.f + expf(-qc));
    }
}

// ---------------- K7: Y = (0.5*yl + y1)*gate, BN stats ----------------
__global__ void k7(const float* __restrict__ We, const float* __restrict__ be) {
    __shared__ float A12ls[150], Wes[512], bes[64], gates[64], ytile[768], zs[3200];
    int n = blockIdx.x, t0 = blockIdx.y * 16, tid = threadIdx.x;
    for (int i = tid; i < 150; i += 256) A12ls[i] = g_A12l[n*150 + i];
    for (int i = tid; i < 512; i += 256) Wes[i] = We[i];
    if (tid < 64) { bes[tid] = be[tid]; gates[tid] = g_gate[n*64 + tid]; }
    for (int i = tid; i < 768; i += 256) {
        int o = i / 96, r = i % 96, t = r / 6, j = r % 6;
        ytile[i] = g_ysm[(n*8 + o)*768 + (t0 + t)*6 + j];
    }
    __syncthreads();
    for (int i = tid; i < 3200; i += 256) {
        int o = i / 400, r = i % 400, t = r / 25, v = r % 25;
        float s = 0.f;
        #pragma unroll
        for (int j = 0; j < 6; j++) s += ytile[o*96 + t*6 + j] * A12ls[j*25 + v];
        zs[i] = s;
    }
    __syncthreads();
    int warp = tid >> 5, lane = tid & 31;
    for (int cc = warp; cc < 64; cc += 8) {
        float wrow[8];
        #pragma unroll
        for (int o = 0; o < 8; o++) wrow[o] = Wes[cc*8 + o];
        float bc = bes[cc], gt = gates[cc];
        float lsy = 0.f, lsyy = 0.f;
        int base = ((n*64 + cc)*128 + t0)*25;
        for (int i = lane; i < 400; i += 32) {
            float yl = bc;
            #pragma unroll
            for (int o = 0; o < 8; o++) yl += wrow[o] * zs[o*400 + i];
            float Y = 0.5f*yl + g_y1[base + i];
            float Yg = Y * gt;
            g_y1[base + i] = Yg;
            lsy += Yg;
            lsyy += Yg * Yg;
        }
        #pragma unroll
        for (int off = 16; off > 0; off >>= 1) {
            lsy  += __shfl_down_sync(0xffffffffu, lsy, off);
            lsyy += __shfl_down_sync(0xffffffffu, lsyy, off);
        }
        if (lane == 0) {
            atomicAdd(&g_SY[cc], lsy);
            atomicAdd(&g_SYY[cc], lsyy);
        }
    }
}

// ---------------- K9: out = relu(BN(Yg) + x), BN params inline ----------------
__global__ void k9(const float* __restrict__ x,
                   const float* __restrict__ bn_g, const float* __restrict__ bn_b,
                   float* __restrict__ out) {
    int i = blockIdx.x * 256 + threadIdx.x;
    if (i >= 3276800) return;
    int c = (i / 800) & 63;
    const float icnt = 1.f/204800.f;
    float mu = g_SY[c] * icnt;
    float var = g_SYY[c] * icnt - mu*mu;
    float sc = bn_g[c] * rsqrtf(var + 1e-5f);
    float sh = bn_b[c] - mu*sc;
    float4 yv = reinterpret_cast<const float4*>(g_y1)[i];
    float4 xv = reinterpret_cast<const float4*>(x)[i];
    float4 o;
    o.x = fmaxf(yv.x*sc + sh + xv.x, 0.f);
    o.y = fmaxf(yv.y*sc + sh + xv.y, 0.f);
    o.z = fmaxf(yv.z*sc + sh + xv.z, 0.f);
    o.w = fmaxf(yv.w*sc + sh + xv.w, 0.f);
    reinterpret_cast<float4*>(out)[i] = o;
}

// ---------------- launch ----------------
extern "C" void kernel_launch(void* const* d_in, const int* in_sizes, int n_in,
                              void* d_out, int out_size) {
    const float* x     = (const float*)d_in[0];
    const float* Dpap  = (const float*)d_in[1];
    const float* pa    = (const float*)d_in[2];
    const float* DecA  = (const float*)d_in[3];
    const float* A1buf = (const float*)d_in[4];
    const float* Wp    = (const float*)d_in[5];
    const float* bp    = (const float*)d_in[6];
    const float* Ws    = (const float*)d_in[7];
    const float* bs    = (const float*)d_in[8];
    const float* W1    = (const float*)d_in[9];
    const float* b1    = (const float*)d_in[10];
    const float* W2    = (const float*)d_in[11];
    const float* b2    = (const float*)d_in[12];
    const float* We    = (const float*)d_in[13];
    const float* be    = (const float*)d_in[14];
    const float* wt1   = (const float*)d_in[15];
    const float* wt2   = (const float*)d_in[16];
    const float* wtw1  = (const float*)d_in[17];
    const float* wtw2  = (const float*)d_in[18];
    const float* wtw11 = (const float*)d_in[19];
    const float* wtw21 = (const float*)d_in[20];
    const float* ws1   = (const float*)d_in[21];
    const float* ws2   = (const float*)d_in[22];
    const float* kca   = (const float*)d_in[23];
    const float* bn_g  = (const float*)d_in[24];
    const float* bn_b  = (const float*)d_in[25];
    float* out = (float*)d_out;

    cudaFuncSetAttribute(k5, cudaFuncAttributeMaxDynamicSharedMemorySize,
                         K5_SMEM_FLOATS * 4);

    k0z<<<400, 256>>>(W2, Ws, b2, bs, Wp, bp, Dpap, pa, DecA, A1buf);
    k1<<<dim3(64, 16), 512>>>(x, Wp, bp);
    k2<<<64, 256>>>(wt1, wt2, wtw1, wtw2, wtw11, wtw21);
    k5<<<dim3(64, 32), 512, K5_SMEM_FLOATS * 4>>>(x);
    k4<<<64, 256>>>(W1, b1);
    k6<<<64, 128>>>(ws1, ws2, We, be, kca);
    k7<<<dim3(64, 8), 256>>>(We, be);
    k9<<<12800, 256>>>(x, bn_g, bn_b, out);
}

// round 6
// speedup vs baseline: 2.2996x; 1.6248x over previous
#include <cuda_runtime.h>
#include <cuda_bf16.h>
#include <math.h>

#define NN 64
#define CC 64
#define TT_ 128
#define VV 25

// ---------------- device scratch ----------------
__device__ float g_x1[NN*8*TT_*VV];
__device__ float g_xbar[NN*1600];
__device__ float g_A12[NN*150];
__device__ float g_att[NN*36];
__device__ float g_att2[NN*625];
__device__ float g_Dful[NN*16800];
__device__ float g_x1gcn[NN*8*TT_*6];
__device__ float g_ysm[NN*8*TT_*6];
__device__ float g_ybarS[NN*6];
__device__ __nv_bfloat16 g_y1[NN*CC*TT_*VV];
__device__ float g_y1sum_nv[NN*VV];
__device__ float g_y1sum_nc[NN*CC];
__device__ float g_A12l[NN*150];
__device__ float g_gate[NN*CC];
__device__ float g_SY[CC], g_SYY[CC];
__device__ float g_WcombT[64*192];
__device__ float g_bcomb[192];
__device__ float g_WpMean[64], g_WsMean[64];
__device__ float g_bpMean[1], g_bsMean[1];
__device__ float g_nlp[864];
__device__ float g_nlA[15000];

__device__ const int c_joints[6] = {3, 20, 7, 11, 14, 18};

// ---------------- K0z: zero accumulators + parallel weight folding ----------------
__global__ void k0z(const float* __restrict__ W2, const float* __restrict__ Ws,
                    const float* __restrict__ b2, const float* __restrict__ bs,
                    const float* __restrict__ Wp, const float* __restrict__ bp,
                    const float* __restrict__ Dpap, const float* __restrict__ pa,
                    const float* __restrict__ DecA, const float* __restrict__ A1buf) {
    int gi = blockIdx.x * 256 + threadIdx.x;
    if (gi < NN*1600) g_xbar[gi] = 0.f;
    if (gi < NN*CC) g_y1sum_nc[gi] = 0.f;
    if (gi < NN*VV) g_y1sum_nv[gi] = 0.f;
    if (gi < CC) { g_SY[gi] = 0.f; g_SYY[gi] = 0.f; }
    int b = blockIdx.x, tid = threadIdx.x;
    if (b < 4) {
        for (int q = tid; q < 3072; q += 256) {
            int idx = b*3072 + q;
            int cj = idx / 192, r = idx % 192;
            float s = 0.f;
            #pragma unroll 8
            for (int cm = 0; cm < 64; cm++) s += W2[r*64 + cm] * Ws[cm*64 + cj];
            g_WcombT[cj*192 + r] = s;
        }
    } else if (b == 4) {
        for (int r = tid; r < 192; r += 256) {
            float s = 0.f;
            for (int cm = 0; cm < 64; cm++) s += W2[r*64 + cm] * bs[cm];
            g_bcomb[r] = s + b2[r];
        }
        for (int ci = tid; ci < 64; ci += 256) {
            float s = 0.f;
            for (int o = 0; o < 8; o++) s += Wp[o*64 + ci];
            g_WpMean[ci] = s * (1.f/8.f);
            float s2 = 0.f;
            for (int c = 0; c < 64; c++) s2 += Ws[c*64 + ci];
            g_WsMean[ci] = s2 * (1.f/64.f);
        }
        if (tid == 0) {
            float s = 0.f; for (int o = 0; o < 8; o++) s += bp[o];
            g_bpMean[0] = s * (1.f/8.f);
            float s2 = 0.f; for (int c = 0; c < 64; c++) s2 += bs[c];
            g_bsMean[0] = s2 * (1.f/64.f);
        }
    } else if (b == 5) {
        for (int i = tid; i < 864; i += 256) g_nlp[i] = Dpap[i] + pa[i];
    } else if (b == 6 || b == 7) {
        int lo = (b - 6) * 7500;
        for (int i = tid; i < 7500; i += 256) g_nlA[lo + i] = A1buf[lo + i] + DecA[lo + i];
    }
}

// ---------------- K1: x1 conv + xbar partial sums ----------------
__global__ void __launch_bounds__(512) k1(const float* __restrict__ x,
                                          const float* __restrict__ Wp,
                                          const float* __restrict__ bp) {
    __shared__ float xt[12800];
    __shared__ float Wps[512];
    __shared__ float bps[8];
    int n = blockIdx.x, t0 = blockIdx.y * 8, tid = threadIdx.x;
    const float4* x4 = reinterpret_cast<const float4*>(x);
    float4* xt4 = reinterpret_cast<float4*>(xt);
    int xbase4 = n*51200 + (t0*25)/4;
    for (int i = tid; i < 3200; i += 512) {
        int ci = i / 50, p4 = i % 50;
        xt4[ci*50 + p4] = x4[xbase4 + ci*800 + p4];
    }
    if (tid < 512) Wps[tid] = Wp[tid];
    if (tid < 8) bps[tid] = bp[tid];
    __syncthreads();
    for (int idx = tid; idx < 1600; idx += 512) {
        int o = idx / 200, p = idx % 200;
        float acc = bps[o];
        #pragma unroll 16
        for (int ci = 0; ci < 64; ci++) acc += Wps[o*64 + ci] * xt[ci*200 + p];
        g_x1[((n*8 + o)*128 + t0)*25 + p] = acc;
    }
    for (int i = tid; i < 1600; i += 512) {
        int ci = i / 25, v = i % 25;
        float s = 0.f;
        #pragma unroll
        for (int tt = 0; tt < 8; tt++) s += xt[ci*200 + tt*25 + v];
        atomicAdd(&g_xbar[n*1600 + i], s);
    }
}

// ---------------- K2: stats + softmaxes + x1_GCN + Dful ----------------
__global__ void k2(const float* wt1p, const float* wt2p, const float* wtw1p,
                   const float* wtw2p, const float* wtw11p, const float* wtw21p) {
    __shared__ float xbs[1600];
    __shared__ float mb[25], xm2s[25], a1s[6], a2s[25], A12s[150], xms[6], at2s[625];
    int n = blockIdx.x, tid = threadIdx.x;
    for (int i = tid; i < 1600; i += 256) xbs[i] = g_xbar[n*1600 + i];
    __syncthreads();
    if (tid < 25) {
        float d1 = 0.f, d2 = 0.f;
        for (int ci = 0; ci < 64; ci++) {
            float xv = xbs[ci*25 + tid] * (1.f/128.f);
            d1 += xv * g_WpMean[ci];
            d2 += xv * g_WsMean[ci];
        }
        mb[tid] = d1 + g_bpMean[0];
        xm2s[tid] = d2 + g_bsMean[0];
    }
    __syncthreads();
    float wt1 = *wt1p, wt2 = *wt2p;
    if (tid < 25) a2s[tid] = fmaxf(wt2 * mb[tid], 0.f);
    if (tid < 6)  a1s[tid] = fmaxf(wt1 * mb[c_joints[tid]], 0.f);
    __syncthreads();
    if (tid < 25) {
        float e[6], mx = -1e30f;
        #pragma unroll
        for (int j = 0; j < 6; j++) { e[j] = a1s[j] * a2s[tid]; mx = fmaxf(mx, e[j]); }
        float sm = 0.f;
        #pragma unroll
        for (int j = 0; j < 6; j++) { e[j] = expf(e[j] - mx); sm += e[j]; }
        float inv = 1.f / sm;
        #pragma unroll
        for (int j = 0; j < 6; j++) {
            float v = e[j] * inv;
            A12s[j*25 + tid] = v;
            g_A12[n*150 + j*25 + tid] = v;
        }
    }
    __syncthreads();
    if (tid < 6) {
        float s = 0.f;
        for (int v = 0; v < 25; v++) s += mb[v] * A12s[tid*25 + v];
        xms[tid] = s;
    }
    __syncthreads();
    float wtw1 = *wtw1p, wtw2 = *wtw2p;
    if (tid < 6) {
        float r2w = fmaxf(wtw2 * xms[tid], 0.f);
        float e[6], mx = -1e30f;
        #pragma unroll
        for (int j = 0; j < 6; j++) { e[j] = fmaxf(wtw1 * xms[j], 0.f) * r2w; mx = fmaxf(mx, e[j]); }
        float sm = 0.f;
        #pragma unroll
        for (int j = 0; j < 6; j++) { e[j] = expf(e[j] - mx); sm += e[j]; }
        float inv = 1.f / sm;
        #pragma unroll
        for (int j = 0; j < 6; j++) g_att[n*36 + j*6 + tid] = e[j] * inv;
    }
    float wtw11 = *wtw11p, wtw21 = *wtw21p;
    if (tid < 25) {
        float r2w = fmaxf(wtw21 * xm2s[tid], 0.f);
        float e[25], mx = -1e30f;
        #pragma unroll
        for (int v = 0; v < 25; v++) { e[v] = fmaxf(wtw11 * xm2s[v], 0.f) * r2w; mx = fmaxf(mx, e[v]); }
        float sm = 0.f;
        #pragma unroll
        for (int v = 0; v < 25; v++) { e[v] = expf(e[v] - mx); sm += e[v]; }
        float inv = 1.f / sm;
        #pragma unroll
        for (int v = 0; v < 25; v++) {
            float val = e[v] * inv;
            at2s[v*25 + tid] = val;
            g_att2[n*625 + v*25 + tid] = val;
        }
    }
    __syncthreads();
    // x1_GCN
    for (int ot = tid; ot < 1024; ot += 256) {
        int o = ot >> 7, t = ot & 127;
        const float* xr = g_x1 + ((n*8 + o)*128 + t)*25;
        float xv[25];
        #pragma unroll
        for (int v = 0; v < 25; v++) xv[v] = xr[v];
        #pragma unroll
        for (int j = 0; j < 6; j++) {
            float s = 0.f;
            #pragma unroll
            for (int v = 0; v < 25; v++) s += xv[v] * A12s[j*25 + v];
            g_x1gcn[((n*8 + o)*128 + t)*6 + j] = s;
        }
    }
    // Dful[n][g][kv][w28] = nlA + 0.5*att2 (padded to 28 in w)
    for (int i = tid; i < 16800; i += 256) {
        int g = i / 2100, r = i % 2100, kv = r / 28, w = r % 28;
        float val = 0.f;
        if (w < 25) {
            int k = kv / 25, v = kv % 25;
            val = g_nlA[((k*8 + g)*25 + v)*25 + w] + 0.5f * at2s[v*25 + w];
        }
        g_Dful[n*16800 + i] = val;
    }
}

// ---------------- K5: heavy y1 kernel ----------------
// smem: Wcs[12288] | Ds[16800] | m2s[192*105] | xt[6400] | red[128] | bcs[192]
#define K5_SMEM_FLOATS (12288 + 16800 + 20160 + 6400 + 128 + 192)
__global__ void __launch_bounds__(512, 1) k5(const float* __restrict__ x) {
    extern __shared__ float sm[];
    float* Wcs = sm;
    float* Ds  = Wcs + 12288;
    float* m2s = Ds + 16800;          // stride 105 per row
    float* xt  = m2s + 20160;
    float* red = xt + 6400;
    float* bcs = red + 128;
    int n = blockIdx.x, t0 = blockIdx.y * 4, tid = threadIdx.x;
    if (tid < 128) red[tid] = 0.f;
    if (tid < 192) bcs[tid] = g_bcomb[tid];
    {
        const float4* Wg4 = reinterpret_cast<const float4*>(g_WcombT);
        float4* Ws4 = reinterpret_cast<float4*>(Wcs);
        for (int i = tid; i < 3072; i += 512) Ws4[i] = Wg4[i];
        const float4* x4 = reinterpret_cast<const float4*>(x);
        float4* xt4 = reinterpret_cast<float4*>(xt);
        int xbase4 = n*51200 + (t0/4)*25;
        for (int i = tid; i < 1600; i += 512) {
            int ci = i / 25, p4 = i % 25;
            xt4[ci*25 + p4] = x4[xbase4 + ci*800 + p4];
        }
        const float4* Dg4 = reinterpret_cast<const float4*>(g_Dful + n*16800);
        float4* Ds4 = reinterpret_cast<float4*>(Ds);
        for (int i = tid; i < 4200; i += 512) Ds4[i] = Dg4[i];
    }
    __syncthreads();
    // phase A: m2[r][p], 400 tiles of 12r x 4p, one per thread
    if (tid < 400) {
        const float4* W4 = reinterpret_cast<const float4*>(Wcs);
        const float4* xt4 = reinterpret_cast<const float4*>(xt);
        int pp = tid % 25, rq = tid / 25;
        float acc[12][4];
        #pragma unroll
        for (int i = 0; i < 12; i++)
            #pragma unroll
            for (int j = 0; j < 4; j++) acc[i][j] = 0.f;
        #pragma unroll 8
        for (int ci = 0; ci < 64; ci++) {
            float4 w0 = W4[ci*48 + rq*3];
            float4 w1 = W4[ci*48 + rq*3 + 1];
            float4 w2 = W4[ci*48 + rq*3 + 2];
            float4 xv = xt4[ci*25 + pp];
            float xa[4] = {xv.x, xv.y, xv.z, xv.w};
            float wa[12] = {w0.x, w0.y, w0.z, w0.w, w1.x, w1.y, w1.z, w1.w,
                            w2.x, w2.y, w2.z, w2.w};
            #pragma unroll
            for (int i = 0; i < 12; i++)
                #pragma unroll
                for (int j = 0; j < 4; j++) acc[i][j] += wa[i]*xa[j];
        }
        int r0 = rq * 12, p0 = pp * 4;
        int tt0 = p0 / 25, v0 = p0 % 25;
        #pragma unroll
        for (int i = 0; i < 12; i++) {
            float bb = bcs[r0 + i];
            int tt = tt0, v = v0;
            #pragma unroll
            for (int j = 0; j < 4; j++) {
                m2s[(r0 + i)*105 + tt*26 + v] = acc[i][j] + bb;
                if (++v == 25) { v = 0; tt++; }
            }
        }
    }
    __syncthreads();
    // phase B: 448 tiles, each 1c x 4t x 4w; results staged into xt
    if (tid < 448) {
        int c = tid & 63, wq = tid >> 6, w0 = wq * 4, g = c & 7;
        float acc[4][4];
        #pragma unroll
        for (int tt = 0; tt < 4; tt++)
            #pragma unroll
            for (int j = 0; j < 4; j++) acc[tt][j] = 0.f;
        #pragma unroll
        for (int k = 0; k < 3; k++) {
            const float* mrow = &m2s[(k*64 + c)*105];
            const float4* dr = reinterpret_cast<const float4*>(&Ds[(g*75 + k*25)*28 + w0]);
            #pragma unroll 5
            for (int v = 0; v < 25; v++) {
                float4 d = dr[v*7];
                float da[4] = {d.x, d.y, d.z, d.w};
                float m0 = mrow[v], m1 = mrow[26 + v], m2v = mrow[52 + v], m3 = mrow[78 + v];
                #pragma unroll
                for (int j = 0; j < 4; j++) {
                    acc[0][j] += m0 * da[j];
                    acc[1][j] += m1 * da[j];
                    acc[2][j] += m2v * da[j];
                    acc[3][j] += m3 * da[j];
                }
            }
        }
        float csum = 0.f;
        #pragma unroll
        for (int j = 0; j < 4; j++) {
            int w = w0 + j;
            if (w < 25) {
                float ws = 0.f;
                #pragma unroll
                for (int tt = 0; tt < 4; tt++) {
                    xt[c*100 + tt*25 + w] = acc[tt][j];
                    ws += acc[tt][j];
                }
                atomicAdd(&red[w], ws);
                csum += ws;
            }
        }
        atomicAdd(&red[32 + c], csum);
    }
    __syncthreads();
    // bf16 writeback of staged tile
    {
        int base = n*204800 + t0*25;
        for (int i = tid; i < 1600; i += 512) {
            int c = i / 25, q4 = i % 25;
            const float4 v = reinterpret_cast<const float4*>(xt)[c*25 + q4];
            __nv_bfloat162 lo = __floats2bfloat162_rn(v.x, v.y);
            __nv_bfloat162 hi = __floats2bfloat162_rn(v.z, v.w);
            __nv_bfloat162* dst = reinterpret_cast<__nv_bfloat162*>(
                g_y1 + base + c*3200 + q4*4);
            dst[0] = lo;
            dst[1] = hi;
        }
    }
    if (tid < 25) atomicAdd(&g_y1sum_nv[n*25 + tid], red[tid]);
    if (tid >= 32 && tid < 96) atomicAdd(&g_y1sum_nc[n*64 + tid - 32], red[tid]);
}

// ---------------- K4: small branch y + ybarS ----------------
__global__ void k4(const float* __restrict__ W1, const float* __restrict__ b1) {
    __shared__ float gcns[6144];
    __shared__ float W1s[192], b1s[24], Efb[864], yred[6];
    int n = blockIdx.x, tid = threadIdx.x;
    for (int i = tid; i < 6144; i += 256) gcns[i] = g_x1gcn[n*6144 + i];
    if (tid < 192) W1s[tid] = W1[tid];
    if (tid < 24) b1s[tid] = b1[tid];
    for (int i = tid; i < 864; i += 256) Efb[i] = 0.5f * g_att[n*36 + (i % 36)] + g_nlp[i];
    if (tid < 6) yred[tid] = 0.f;
    __syncthreads();
    float lsum[6] = {0.f, 0.f, 0.f, 0.f, 0.f, 0.f};
    for (int gt = tid; gt < 1024; gt += 256) {
        int g = gt >> 7, t = gt & 127;
        float mloc[3][6];
        #pragma unroll
        for (int k = 0; k < 3; k++) {
            const float* wrow = &W1s[(k*8 + g)*8];
            float bb = b1s[k*8 + g];
            #pragma unroll
            for (int j = 0; j < 6; j++) {
                float s = bb;
                #pragma unroll
                for (int o = 0; o < 8; o++) s += gcns[(o*128 + t)*6 + j] * wrow[o];
                mloc[k][j] = s;
            }
        }
        #pragma unroll
        for (int w = 0; w < 6; w++) {
            float s = 0.f;
            #pragma unroll
            for (int k = 0; k < 3; k++)
                #pragma unroll
                for (int j = 0; j < 6; j++)
                    s += mloc[k][j] * Efb[((k*8 + g)*6 + j)*6 + w];
            g_ysm[(n*8 + g)*768 + t*6 + w] = s;
            lsum[w] += s;
        }
    }
    #pragma unroll
    for (int w = 0; w < 6; w++) atomicAdd(&yred[w], lsum[w]);
    __syncthreads();
    if (tid < 6) g_ybarS[n*6 + tid] = yred[tid] * (1.f/1024.f);
}

// ---------------- K6: A12l + channel gate ----------------
__global__ void k6(const float* ws1p, const float* ws2p,
                   const float* __restrict__ We, const float* __restrict__ be,
                   const float* __restrict__ kca) {
    __shared__ float a1ls[6], A12ls[150], ytsum[48], Asum[6], Ssum[8], qs[64];
    int n = blockIdx.x, tid = threadIdx.x;
    if (tid < 6) a1ls[tid] = fmaxf((*ws1p) * g_ybarS[n*6 + tid], 0.f);
    __syncthreads();
    if (tid < 25) {
        float a2 = fmaxf((*ws2p) * g_y1sum_nv[n*25 + tid] * (1.f/8192.f), 0.f);
        float e[6], mx = -1e30f;
        #pragma unroll
        for (int j = 0; j < 6; j++) { e[j] = a1ls[j] * a2; mx = fmaxf(mx, e[j]); }
        float s = 0.f;
        #pragma unroll
        for (int j = 0; j < 6; j++) { e[j] = expf(e[j] - mx); s += e[j]; }
        float inv = 1.f / s;
        #pragma unroll
        for (int j = 0; j < 6; j++) {
            float v = e[j] * inv;
            A12ls[j*25 + tid] = v;
            g_A12l[n*150 + j*25 + tid] = v;
        }
    }
    for (int i = tid; i < 48; i += 128) {
        int o = i / 6, j = i % 6;
        float s = 0.f;
        for (int t = 0; t < 128; t++) s += g_ysm[(n*8 + o)*768 + t*6 + j];
        ytsum[i] = s;
    }
    __syncthreads();
    if (tid < 6) {
        float s = 0.f;
        for (int v = 0; v < 25; v++) s += A12ls[tid*25 + v];
        Asum[tid] = s;
    }
    __syncthreads();
    if (tid < 8) {
        float s = 0.f;
        #pragma unroll
        for (int j = 0; j < 6; j++) s += ytsum[tid*6 + j] * Asum[j];
        Ssum[tid] = s;
    }
    __syncthreads();
    if (tid < 64) {
        float yls = 3200.f * be[tid];
        #pragma unroll
        for (int o = 0; o < 8; o++) yls += We[tid*8 + o] * Ssum[o];
        qs[tid] = (g_y1sum_nc[n*64 + tid] + 0.5f * yls) * (1.f/3200.f);
    }
    __syncthreads();
    if (tid < 64) {
        float qm = (tid > 0) ? qs[tid-1] : 0.f;
        float q0 = qs[tid];
        float qp1 = (tid < 63) ? qs[tid+1] : 0.f;
        float qc = kca[0]*qm + kca[1]*q0 + kca[2]*qp1;
        g_gate[n*64 + tid] = 1.f + 1.f/(1.f + expf(-qc));
    }
}

// ---------------- K7: Y = (0.5*yl + y1)*gate, BN stats (bf16 y1) ----------------
__global__ void k7(const float* __restrict__ We, const float* __restrict__ be) {
    __shared__ float A12ls[150], Wes[512], bes[64], gates[64], ytile[768], zs[3200];
    int n = blockIdx.x, t0 = blockIdx.y * 16, tid = threadIdx.x;
    for (int i = tid; i < 150; i += 256) A12ls[i] = g_A12l[n*150 + i];
    for (int i = tid; i < 512; i += 256) Wes[i] = We[i];
    if (tid < 64) { bes[tid] = be[tid]; gates[tid] = g_gate[n*64 + tid]; }
    for (int i = tid; i < 768; i += 256) {
        int o = i / 96, r = i % 96, t = r / 6, j = r % 6;
        ytile[i] = g_ysm[(n*8 + o)*768 + (t0 + t)*6 + j];
    }
    __syncthreads();
    for (int i = tid; i < 3200; i += 256) {
        int o = i / 400, r = i % 400, t = r / 25, v = r % 25;
        float s = 0.f;
        #pragma unroll
        for (int j = 0; j < 6; j++) s += ytile[o*96 + t*6 + j] * A12ls[j*25 + v];
        zs[i] = s;
    }
    __syncthreads();
    int warp = tid >> 5, lane = tid & 31;
    for (int cc = warp; cc < 64; cc += 8) {
        float wrow[8];
        #pragma unroll
        for (int o = 0; o < 8; o++) wrow[o] = Wes[cc*8 + o];
        float bc = bes[cc], gt = gates[cc];
        float lsy = 0.f, lsyy = 0.f;
        int base = ((n*64 + cc)*128 + t0)*25;
        __nv_bfloat162* y2 = reinterpret_cast<__nv_bfloat162*>(g_y1 + base);
        for (int i2 = lane; i2 < 200; i2 += 32) {
            int e0 = 2*i2, e1 = e0 + 1;
            float yl0 = bc, yl1 = bc;
            #pragma unroll
            for (int o = 0; o < 8; o++) {
                yl0 += wrow[o] * zs[o*400 + e0];
                yl1 += wrow[o] * zs[o*400 + e1];
            }
            __nv_bfloat162 yv = y2[i2];
            float Y0 = (0.5f*yl0 + __bfloat162float(yv.x)) * gt;
            float Y1 = (0.5f*yl1 + __bfloat162float(yv.y)) * gt;
            y2[i2] = __floats2bfloat162_rn(Y0, Y1);
            lsy += Y0 + Y1;
            lsyy += Y0*Y0 + Y1*Y1;
        }
        #pragma unroll
        for (int off = 16; off > 0; off >>= 1) {
            lsy  += __shfl_down_sync(0xffffffffu, lsy, off);
            lsyy += __shfl_down_sync(0xffffffffu, lsyy, off);
        }
        if (lane == 0) {
            atomicAdd(&g_SY[cc], lsy);
            atomicAdd(&g_SYY[cc], lsyy);
        }
    }
}

// ---------------- K9: out = relu(BN(Yg) + x), BN inline ----------------
__global__ void k9(const float* __restrict__ x,
                   const float* __restrict__ bn_g, const float* __restrict__ bn_b,
                   float* __restrict__ out) {
    int i = blockIdx.x * 256 + threadIdx.x;
    if (i >= 3276800) return;
    int c = (i / 800) & 63;
    const float icnt = 1.f/204800.f;
    float mu = g_SY[c] * icnt;
    float var = g_SYY[c] * icnt - mu*mu;
    float sc = bn_g[c] * rsqrtf(var + 1e-5f);
    float sh = bn_b[c] - mu*sc;
    const __nv_bfloat162* y2 = reinterpret_cast<const __nv_bfloat162*>(g_y1);
    __nv_bfloat162 ya = y2[i*2], yb = y2[i*2 + 1];
    float4 xv = reinterpret_cast<const float4*>(x)[i];
    float4 o;
    o.x = fmaxf(__bfloat162float(ya.x)*sc + sh + xv.x, 0.f);
    o.y = fmaxf(__bfloat162float(ya.y)*sc + sh + xv.y, 0.f);
    o.z = fmaxf(__bfloat162float(yb.x)*sc + sh + xv.z, 0.f);
    o.w = fmaxf(__bfloat162float(yb.y)*sc + sh + xv.w, 0.f);
    reinterpret_cast<float4*>(out)[i] = o;
}

// ---------------- launch ----------------
extern "C" void kernel_launch(void* const* d_in, const int* in_sizes, int n_in,
                              void* d_out, int out_size) {
    const float* x     = (const float*)d_in[0];
    const float* Dpap  = (const float*)d_in[1];
    const float* pa    = (const float*)d_in[2];
    const float* DecA  = (const float*)d_in[3];
    const float* A1buf = (const float*)d_in[4];
    const float* Wp    = (const float*)d_in[5];
    const float* bp    = (const float*)d_in[6];
    const float* Ws    = (const float*)d_in[7];
    const float* bs    = (const float*)d_in[8];
    const float* W1    = (const float*)d_in[9];
    const float* b1    = (const float*)d_in[10];
    const float* W2    = (const float*)d_in[11];
    const float* b2    = (const float*)d_in[12];
    const float* We    = (const float*)d_in[13];
    const float* be    = (const float*)d_in[14];
    const float* wt1   = (const float*)d_in[15];
    const float* wt2   = (const float*)d_in[16];
    const float* wtw1  = (const float*)d_in[17];
    const float* wtw2  = (const float*)d_in[18];
    const float* wtw11 = (const float*)d_in[19];
    const float* wtw21 = (const float*)d_in[20];
    const float* ws1   = (const float*)d_in[21];
    const float* ws2   = (const float*)d_in[22];
    const float* kca   = (const float*)d_in[23];
    const float* bn_g  = (const float*)d_in[24];
    const float* bn_b  = (const float*)d_in[25];
    float* out = (float*)d_out;

    cudaFuncSetAttribute(k5, cudaFuncAttributeMaxDynamicSharedMemorySize,
                         K5_SMEM_FLOATS * 4);

    k0z<<<400, 256>>>(W2, Ws, b2, bs, Wp, bp, Dpap, pa, DecA, A1buf);
    k1<<<dim3(64, 16), 512>>>(x, Wp, bp);
    k2<<<64, 256>>>(wt1, wt2, wtw1, wtw2, wtw11, wtw21);
    k5<<<dim3(64, 32), 512, K5_SMEM_FLOATS * 4>>>(x);
    k4<<<64, 256>>>(W1, b1);
    k6<<<64, 128>>>(ws1, ws2, We, be, kca);
    k7<<<dim3(64, 8), 256>>>(We, be);
    k9<<<12800, 256>>>(x, bn_g, bn_b, out);
}

// round 7
// speedup vs baseline: 2.4568x; 1.0684x over previous
#include <cuda_runtime.h>
#include <cuda_bf16.h>
#include <math.h>

#define NN 64
#define CC 64
#define TT_ 128
#define VV 25

// ---------------- device scratch ----------------
__device__ float g_x1[NN*8*TT_*VV];
__device__ float g_xbar[NN*1600];
__device__ float g_A12[NN*150];
__device__ float g_att[NN*36];
__device__ __nv_bfloat162 g_D2[NN*9632];     // packed (w,w+1) pairs, per-g stride 1204
__device__ float g_x1gcn[NN*8*TT_*6];
__device__ float g_ysm[NN*8*TT_*6];
__device__ float g_ybarS[NN*6];
__device__ __nv_bfloat16 g_y1[NN*CC*TT_*VV];
__device__ float g_y1sum_nv[NN*VV];
__device__ float g_y1sum_nc[NN*CC];
__device__ float g_A12l[NN*150];
__device__ float g_gate[NN*CC];
__device__ float g_SY[CC], g_SYY[CC];
__device__ __nv_bfloat162 g_Wc2[64*192];     // Wcomb duplicated (w,w), layout [ci][192]
__device__ __nv_bfloat162 g_bc2[192];
__device__ float g_WpMean[64], g_WsMean[64];
__device__ float g_bpMean[1], g_bsMean[1];
__device__ float g_nlp[864];
__device__ float g_nlA[15000];

__device__ const int c_joints[6] = {3, 20, 7, 11, 14, 18};

__device__ __forceinline__ __nv_bfloat162 u2b(unsigned u) {
    union { unsigned u; __nv_bfloat162 b; } cv; cv.u = u; return cv.b;
}

// ---------------- K0z: zero accumulators + parallel weight folding ----------------
__global__ void k0z(const float* __restrict__ W2, const float* __restrict__ Ws,
                    const float* __restrict__ b2, const float* __restrict__ bs,
                    const float* __restrict__ Wp, const float* __restrict__ bp,
                    const float* __restrict__ Dpap, const float* __restrict__ pa,
                    const float* __restrict__ DecA, const float* __restrict__ A1buf) {
    int gi = blockIdx.x * 256 + threadIdx.x;
    if (gi < NN*1600) g_xbar[gi] = 0.f;
    if (gi < NN*CC) g_y1sum_nc[gi] = 0.f;
    if (gi < NN*VV) g_y1sum_nv[gi] = 0.f;
    if (gi < CC) { g_SY[gi] = 0.f; g_SYY[gi] = 0.f; }
    int b = blockIdx.x, tid = threadIdx.x;
    if (b < 4) {
        for (int q = tid; q < 3072; q += 256) {
            int idx = b*3072 + q;
            int cj = idx / 192, r = idx % 192;
            float s = 0.f;
            #pragma unroll 8
            for (int cm = 0; cm < 64; cm++) s += W2[r*64 + cm] * Ws[cm*64 + cj];
            g_Wc2[cj*192 + r] = __bfloat162bfloat162(__float2bfloat16(s));
        }
    } else if (b == 4) {
        for (int r = tid; r < 192; r += 256) {
            float s = 0.f;
            for (int cm = 0; cm < 64; cm++) s += W2[r*64 + cm] * bs[cm];
            g_bc2[r] = __bfloat162bfloat162(__float2bfloat16(s + b2[r]));
        }
        for (int ci = tid; ci < 64; ci += 256) {
            float s = 0.f;
            for (int o = 0; o < 8; o++) s += Wp[o*64 + ci];
            g_WpMean[ci] = s * (1.f/8.f);
            float s2 = 0.f;
            for (int c = 0; c < 64; c++) s2 += Ws[c*64 + ci];
            g_WsMean[ci] = s2 * (1.f/64.f);
        }
        if (tid == 0) {
            float s = 0.f; for (int o = 0; o < 8; o++) s += bp[o];
            g_bpMean[0] = s * (1.f/8.f);
            float s2 = 0.f; for (int c = 0; c < 64; c++) s2 += bs[c];
            g_bsMean[0] = s2 * (1.f/64.f);
        }
    } else if (b == 5) {
        for (int i = tid; i < 864; i += 256) g_nlp[i] = Dpap[i] + pa[i];
    } else if (b == 6 || b == 7) {
        int lo = (b - 6) * 7500;
        for (int i = tid; i < 7500; i += 256) g_nlA[lo + i] = A1buf[lo + i] + DecA[lo + i];
    }
}

// ---------------- K1: x1 conv + xbar partial sums ----------------
__global__ void __launch_bounds__(512) k1(const float* __restrict__ x,
                                          const float* __restrict__ Wp,
                                          const float* __restrict__ bp) {
    __shared__ float xt[12800];
    __shared__ float Wps[512];
    __shared__ float bps[8];
    int n = blockIdx.x, t0 = blockIdx.y * 8, tid = threadIdx.x;
    const float4* x4 = reinterpret_cast<const float4*>(x);
    float4* xt4 = reinterpret_cast<float4*>(xt);
    int xbase4 = n*51200 + (t0*25)/4;
    for (int i = tid; i < 3200; i += 512) {
        int ci = i / 50, p4 = i % 50;
        xt4[ci*50 + p4] = x4[xbase4 + ci*800 + p4];
    }
    if (tid < 512) Wps[tid] = Wp[tid];
    if (tid < 8) bps[tid] = bp[tid];
    __syncthreads();
    for (int idx = tid; idx < 1600; idx += 512) {
        int o = idx / 200, p = idx % 200;
        float acc = bps[o];
        #pragma unroll 16
        for (int ci = 0; ci < 64; ci++) acc += Wps[o*64 + ci] * xt[ci*200 + p];
        g_x1[((n*8 + o)*128 + t0)*25 + p] = acc;
    }
    for (int i = tid; i < 1600; i += 512) {
        int ci = i / 25, v = i % 25;
        float s = 0.f;
        #pragma unroll
        for (int tt = 0; tt < 8; tt++) s += xt[ci*200 + tt*25 + v];
        atomicAdd(&g_xbar[n*1600 + i], s);
    }
}

// ---------------- K2: stats + softmaxes + x1_GCN + D2 pack ----------------
__global__ void k2(const float* wt1p, const float* wt2p, const float* wtw1p,
                   const float* wtw2p, const float* wtw11p, const float* wtw21p) {
    __shared__ float xbs[1600];
    __shared__ float mb[25], xm2s[25], a1s[6], a2s[25], A12s[150], xms[6], at2s[625];
    int n = blockIdx.x, tid = threadIdx.x;
    for (int i = tid; i < 1600; i += 256) xbs[i] = g_xbar[n*1600 + i];
    __syncthreads();
    if (tid < 25) {
        float d1 = 0.f, d2 = 0.f;
        for (int ci = 0; ci < 64; ci++) {
            float xv = xbs[ci*25 + tid] * (1.f/128.f);
            d1 += xv * g_WpMean[ci];
            d2 += xv * g_WsMean[ci];
        }
        mb[tid] = d1 + g_bpMean[0];
        xm2s[tid] = d2 + g_bsMean[0];
    }
    __syncthreads();
    float wt1 = *wt1p, wt2 = *wt2p;
    if (tid < 25) a2s[tid] = fmaxf(wt2 * mb[tid], 0.f);
    if (tid < 6)  a1s[tid] = fmaxf(wt1 * mb[c_joints[tid]], 0.f);
    __syncthreads();
    if (tid < 25) {
        float e[6], mx = -1e30f;
        #pragma unroll
        for (int j = 0; j < 6; j++) { e[j] = a1s[j] * a2s[tid]; mx = fmaxf(mx, e[j]); }
        float sm = 0.f;
        #pragma unroll
        for (int j = 0; j < 6; j++) { e[j] = expf(e[j] - mx); sm += e[j]; }
        float inv = 1.f / sm;
        #pragma unroll
        for (int j = 0; j < 6; j++) {
            float v = e[j] * inv;
            A12s[j*25 + tid] = v;
            g_A12[n*150 + j*25 + tid] = v;
        }
    }
    __syncthreads();
    if (tid < 6) {
        float s = 0.f;
        for (int v = 0; v < 25; v++) s += mb[v] * A12s[tid*25 + v];
        xms[tid] = s;
    }
    __syncthreads();
    float wtw1 = *wtw1p, wtw2 = *wtw2p;
    if (tid < 6) {
        float r2w = fmaxf(wtw2 * xms[tid], 0.f);
        float e[6], mx = -1e30f;
        #pragma unroll
        for (int j = 0; j < 6; j++) { e[j] = fmaxf(wtw1 * xms[j], 0.f) * r2w; mx = fmaxf(mx, e[j]); }
        float sm = 0.f;
        #pragma unroll
        for (int j = 0; j < 6; j++) { e[j] = expf(e[j] - mx); sm += e[j]; }
        float inv = 1.f / sm;
        #pragma unroll
        for (int j = 0; j < 6; j++) g_att[n*36 + j*6 + tid] = e[j] * inv;
    }
    float wtw11 = *wtw11p, wtw21 = *wtw21p;
    if (tid < 25) {
        float r2w = fmaxf(wtw21 * xm2s[tid], 0.f);
        float e[25], mx = -1e30f;
        #pragma unroll
        for (int v = 0; v < 25; v++) { e[v] = fmaxf(wtw11 * xm2s[v], 0.f) * r2w; mx = fmaxf(mx, e[v]); }
        float sm = 0.f;
        #pragma unroll
        for (int v = 0; v < 25; v++) { e[v] = expf(e[v] - mx); sm += e[v]; }
        float inv = 1.f / sm;
        #pragma unroll
        for (int v = 0; v < 25; v++) at2s[v*25 + tid] = e[v] * inv;
    }
    __syncthreads();
    // x1_GCN
    for (int ot = tid; ot < 1024; ot += 256) {
        int o = ot >> 7, t = ot & 127;
        const float* xr = g_x1 + ((n*8 + o)*128 + t)*25;
        float xv[25];
        #pragma unroll
        for (int v = 0; v < 25; v++) xv[v] = xr[v];
        #pragma unroll
        for (int j = 0; j < 6; j++) {
            float s = 0.f;
            #pragma unroll
            for (int v = 0; v < 25; v++) s += xv[v] * A12s[j*25 + v];
            g_x1gcn[((n*8 + o)*128 + t)*6 + j] = s;
        }
    }
    // D2 pack: [g][kv*16 + w2] with per-g stride 1204, (w, w+1) bf16x2
    for (int i = tid; i < 9632; i += 256) {
        int g = i / 1204, r = i % 1204;
        int kv = r >> 4, w2 = r & 15;
        float v0 = 0.f, v1 = 0.f;
        if (kv < 75) {
            int k = kv / 25, v = kv % 25;
            int w0 = w2*2, w1 = w0 + 1;
            if (w0 < 25) v0 = g_nlA[((k*8 + g)*25 + v)*25 + w0] + 0.5f * at2s[v*25 + w0];
            if (w1 < 25) v1 = g_nlA[((k*8 + g)*25 + v)*25 + w1] + 0.5f * at2s[v*25 + w1];
        }
        g_D2[n*9632 + i] = __floats2bfloat162_rn(v0, v1);
    }
}

// ---------------- K5: heavy y1 kernel, bf16x2 HFMA2, t-tile 8 ----------------
#define K5_W_OFF 0
#define K5_D_OFF 49152
#define K5_M_OFF 87680
#define K5_X_OFF 165248
#define K5_R_OFF 191872
#define K5_SMEM_BYTES 192384
__global__ void __launch_bounds__(512, 1) k5(const float* __restrict__ x) {
    extern __shared__ char smem[];
    __nv_bfloat162* Wc2s = reinterpret_cast<__nv_bfloat162*>(smem + K5_W_OFF);
    __nv_bfloat162* D2s  = reinterpret_cast<__nv_bfloat162*>(smem + K5_D_OFF);
    __nv_bfloat16*  m2s  = reinterpret_cast<__nv_bfloat16*>(smem + K5_M_OFF);
    __nv_bfloat162* xt2  = reinterpret_cast<__nv_bfloat162*>(smem + K5_X_OFF);
    __nv_bfloat16*  ybuf = reinterpret_cast<__nv_bfloat16*>(smem + K5_X_OFF);
    float* red = reinterpret_cast<float*>(smem + K5_R_OFF);
    int n = blockIdx.x, t0 = blockIdx.y * 8, tid = threadIdx.x;
    if (tid < 128) red[tid] = 0.f;
    {
        const uint4* Wg = reinterpret_cast<const uint4*>(g_Wc2);
        uint4* Wd = reinterpret_cast<uint4*>(Wc2s);
        for (int i = tid; i < 3072; i += 512) Wd[i] = Wg[i];
        const uint4* Dg = reinterpret_cast<const uint4*>(g_D2 + n*9632);
        uint4* Dd = reinterpret_cast<uint4*>(D2s);
        for (int i = tid; i < 2408; i += 512) Dd[i] = Dg[i];
        const float4* x4 = reinterpret_cast<const float4*>(x);
        int xb = n*51200 + (t0*25)/4;
        for (int i = tid; i < 3200; i += 512) {
            int ci = i / 50, q = i % 50;
            float4 v = x4[xb + ci*800 + q];
            xt2[ci*104 + q*2]     = __floats2bfloat162_rn(v.x, v.y);
            xt2[ci*104 + q*2 + 1] = __floats2bfloat162_rn(v.z, v.w);
        }
    }
    __syncthreads();
    // phase A: m2[192][200] = Wcomb @ x, 400 threads, tile 12r x 8p (4 p-pairs)
    if (tid < 400) {
        int pp = tid % 25, rq = tid / 25;
        __nv_bfloat162 acc[12][4];
        #pragma unroll
        for (int i = 0; i < 12; i++)
            #pragma unroll
            for (int j = 0; j < 4; j++) acc[i][j] = u2b(0u);
        const uint4* Wv = reinterpret_cast<const uint4*>(Wc2s);
        const uint4* Xv = reinterpret_cast<const uint4*>(xt2);
        #pragma unroll 4
        for (int ci = 0; ci < 64; ci++) {
            uint4 wa = Wv[ci*48 + rq*3];
            uint4 wb = Wv[ci*48 + rq*3 + 1];
            uint4 wc = Wv[ci*48 + rq*3 + 2];
            uint4 xq = Xv[ci*26 + pp];
            __nv_bfloat162 xr[4] = {u2b(xq.x), u2b(xq.y), u2b(xq.z), u2b(xq.w)};
            __nv_bfloat162 wr[12] = {u2b(wa.x), u2b(wa.y), u2b(wa.z), u2b(wa.w),
                                     u2b(wb.x), u2b(wb.y), u2b(wb.z), u2b(wb.w),
                                     u2b(wc.x), u2b(wc.y), u2b(wc.z), u2b(wc.w)};
            #pragma unroll
            for (int i = 0; i < 12; i++)
                #pragma unroll
                for (int j = 0; j < 4; j++)
                    acc[i][j] = __hfma2(wr[i], xr[j], acc[i][j]);
        }
        int r0 = rq * 12;
        #pragma unroll
        for (int i = 0; i < 12; i++) {
            __nv_bfloat162 bb = g_bc2[r0 + i];
            #pragma unroll
            for (int j = 0; j < 4; j++) {
                *reinterpret_cast<__nv_bfloat162*>(m2s + (r0 + i)*202 + pp*8 + 2*j)
                    = __hadd2(acc[i][j], bb);
            }
        }
    }
    __syncthreads();
    // phase B: 256 threads, tile 1c x 8t x 8w (4 w-pairs)
    if (tid < 256) {
        int c = tid & 63, wq = tid >> 6, g = c & 7;
        __nv_bfloat162 acc[8][4];
        #pragma unroll
        for (int tt = 0; tt < 8; tt++)
            #pragma unroll
            for (int j = 0; j < 4; j++) acc[tt][j] = u2b(0u);
        const uint4* Dv = reinterpret_cast<const uint4*>(D2s);
        #pragma unroll
        for (int k = 0; k < 3; k++) {
            const __nv_bfloat16* mrow = m2s + (k*64 + c)*202;
            const uint4* db = Dv + g*301 + k*100 + wq;
            #pragma unroll 5
            for (int v = 0; v < 25; v++) {
                uint4 dq = db[v*4];
                __nv_bfloat162 d0 = u2b(dq.x), d1 = u2b(dq.y),
                               d2 = u2b(dq.z), d3 = u2b(dq.w);
                #pragma unroll
                for (int tt = 0; tt < 8; tt++) {
                    __nv_bfloat162 m = __bfloat162bfloat162(mrow[tt*25 + v]);
                    acc[tt][0] = __hfma2(m, d0, acc[tt][0]);
                    acc[tt][1] = __hfma2(m, d1, acc[tt][1]);
                    acc[tt][2] = __hfma2(m, d2, acc[tt][2]);
                    acc[tt][3] = __hfma2(m, d3, acc[tt][3]);
                }
            }
        }
        float csum = 0.f;
        #pragma unroll
        for (int j = 0; j < 4; j++) {
            int w0 = wq*8 + 2*j;
            if (w0 > 24) continue;
            float s0 = 0.f, s1 = 0.f;
            #pragma unroll
            for (int tt = 0; tt < 8; tt++) {
                *reinterpret_cast<__nv_bfloat162*>(ybuf + (c*8 + tt)*26 + w0) = acc[tt][j];
                float2 f = __bfloat1622float2(acc[tt][j]);
                s0 += f.x; s1 += f.y;
            }
            atomicAdd(&red[w0], s0);
            csum += s0;
            if (w0 + 1 < 25) { atomicAdd(&red[w0 + 1], s1); csum += s1; }
        }
        atomicAdd(&red[32 + c], csum);
    }
    __syncthreads();
    // writeback: one thread per (c, tt) row
    {
        int c = tid >> 3, tt = tid & 7;
        const __nv_bfloat16* src = ybuf + (c*8 + tt)*26;
        __nv_bfloat16* dst = g_y1 + n*204800 + c*3200 + (t0 + tt)*25;
        #pragma unroll
        for (int v = 0; v < 25; v++) dst[v] = src[v];
    }
    if (tid < 25) atomicAdd(&g_y1sum_nv[n*25 + tid], red[tid]);
    if (tid >= 32 && tid < 96) atomicAdd(&g_y1sum_nc[n*64 + tid - 32], red[tid]);
}

// ---------------- K4: small branch y + ybarS ----------------
__global__ void k4(const float* __restrict__ W1, const float* __restrict__ b1) {
    __shared__ float gcns[6144];
    __shared__ float W1s[192], b1s[24], Efb[864], yred[6];
    int n = blockIdx.x, tid = threadIdx.x;
    for (int i = tid; i < 6144; i += 256) gcns[i] = g_x1gcn[n*6144 + i];
    if (tid < 192) W1s[tid] = W1[tid];
    if (tid < 24) b1s[tid] = b1[tid];
    for (int i = tid; i < 864; i += 256) Efb[i] = 0.5f * g_att[n*36 + (i % 36)] + g_nlp[i];
    if (tid < 6) yred[tid] = 0.f;
    __syncthreads();
    float lsum[6] = {0.f, 0.f, 0.f, 0.f, 0.f, 0.f};
    for (int gt = tid; gt < 1024; gt += 256) {
        int g = gt >> 7, t = gt & 127;
        float mloc[3][6];
        #pragma unroll
        for (int k = 0; k < 3; k++) {
            const float* wrow = &W1s[(k*8 + g)*8];
            float bb = b1s[k*8 + g];
            #pragma unroll
            for (int j = 0; j < 6; j++) {
                float s = bb;
                #pragma unroll
                for (int o = 0; o < 8; o++) s += gcns[(o*128 + t)*6 + j] * wrow[o];
                mloc[k][j] = s;
            }
        }
        #pragma unroll
        for (int w = 0; w < 6; w++) {
            float s = 0.f;
            #pragma unroll
            for (int k = 0; k < 3; k++)
                #pragma unroll
                for (int j = 0; j < 6; j++)
                    s += mloc[k][j] * Efb[((k*8 + g)*6 + j)*6 + w];
            g_ysm[(n*8 + g)*768 + t*6 + w] = s;
            lsum[w] += s;
        }
    }
    #pragma unroll
    for (int w = 0; w < 6; w++) atomicAdd(&yred[w], lsum[w]);
    __syncthreads();
    if (tid < 6) g_ybarS[n*6 + tid] = yred[tid] * (1.f/1024.f);
}

// ---------------- K6: A12l + channel gate ----------------
__global__ void k6(const float* ws1p, const float* ws2p,
                   const float* __restrict__ We, const float* __restrict__ be,
                   const float* __restrict__ kca) {
    __shared__ float a1ls[6], A12ls[150], ytsum[48], Asum[6], Ssum[8], qs[64];
    int n = blockIdx.x, tid = threadIdx.x;
    if (tid < 6) a1ls[tid] = fmaxf((*ws1p) * g_ybarS[n*6 + tid], 0.f);
    __syncthreads();
    if (tid < 25) {
        float a2 = fmaxf((*ws2p) * g_y1sum_nv[n*25 + tid] * (1.f/8192.f), 0.f);
        float e[6], mx = -1e30f;
        #pragma unroll
        for (int j = 0; j < 6; j++) { e[j] = a1ls[j] * a2; mx = fmaxf(mx, e[j]); }
        float s = 0.f;
        #pragma unroll
        for (int j = 0; j < 6; j++) { e[j] = expf(e[j] - mx); s += e[j]; }
        float inv = 1.f / s;
        #pragma unroll
        for (int j = 0; j < 6; j++) {
            float v = e[j] * inv;
            A12ls[j*25 + tid] = v;
            g_A12l[n*150 + j*25 + tid] = v;
        }
    }
    for (int i = tid; i < 48; i += 128) {
        int o = i / 6, j = i % 6;
        float s = 0.f;
        for (int t = 0; t < 128; t++) s += g_ysm[(n*8 + o)*768 + t*6 + j];
        ytsum[i] = s;
    }
    __syncthreads();
    if (tid < 6) {
        float s = 0.f;
        for (int v = 0; v < 25; v++) s += A12ls[tid*25 + v];
        Asum[tid] = s;
    }
    __syncthreads();
    if (tid < 8) {
        float s = 0.f;
        #pragma unroll
        for (int j = 0; j < 6; j++) s += ytsum[tid*6 + j] * Asum[j];
        Ssum[tid] = s;
    }
    __syncthreads();
    if (tid < 64) {
        float yls = 3200.f * be[tid];
        #pragma unroll
        for (int o = 0; o < 8; o++) yls += We[tid*8 + o] * Ssum[o];
        qs[tid] = (g_y1sum_nc[n*64 + tid] + 0.5f * yls) * (1.f/3200.f);
    }
    __syncthreads();
    if (tid < 64) {
        float qm = (tid > 0) ? qs[tid-1] : 0.f;
        float q0 = qs[tid];
        float qp1 = (tid < 63) ? qs[tid+1] : 0.f;
        float qc = kca[0]*qm + kca[1]*q0 + kca[2]*qp1;
        g_gate[n*64 + tid] = 1.f + 1.f/(1.f + expf(-qc));
    }
}

// ---------------- K7: Y = (0.5*yl + y1)*gate, BN stats (bf16 y1) ----------------
__global__ void k7(const float* __restrict__ We, const float* __restrict__ be) {
    __shared__ float A12ls[150], Wes[512], bes[64], gates[64], ytile[768], zs[3200];
    int n = blockIdx.x, t0 = blockIdx.y * 16, tid = threadIdx.x;
    for (int i = tid; i < 150; i += 256) A12ls[i] = g_A12l[n*150 + i];
    for (int i = tid; i < 512; i += 256) Wes[i] = We[i];
    if (tid < 64) { bes[tid] = be[tid]; gates[tid] = g_gate[n*64 + tid]; }
    for (int i = tid; i < 768; i += 256) {
        int o = i / 96, r = i % 96, t = r / 6, j = r % 6;
        ytile[i] = g_ysm[(n*8 + o)*768 + (t0 + t)*6 + j];
    }
    __syncthreads();
    for (int i = tid; i < 3200; i += 256) {
        int o = i / 400, r = i % 400, t = r / 25, v = r % 25;
        float s = 0.f;
        #pragma unroll
        for (int j = 0; j < 6; j++) s += ytile[o*96 + t*6 + j] * A12ls[j*25 + v];
        zs[i] = s;
    }
    __syncthreads();
    int warp = tid >> 5, lane = tid & 31;
    for (int cc = warp; cc < 64; cc += 8) {
        float wrow[8];
        #pragma unroll
        for (int o = 0; o < 8; o++) wrow[o] = Wes[cc*8 + o];
        float bc = bes[cc], gt = gates[cc];
        float lsy = 0.f, lsyy = 0.f;
        int base = ((n*64 + cc)*128 + t0)*25;
        __nv_bfloat162* y2 = reinterpret_cast<__nv_bfloat162*>(g_y1 + base);
        for (int i2 = lane; i2 < 200; i2 += 32) {
            int e0 = 2*i2, e1 = e0 + 1;
            float yl0 = bc, yl1 = bc;
            #pragma unroll
            for (int o = 0; o < 8; o++) {
                yl0 += wrow[o] * zs[o*400 + e0];
                yl1 += wrow[o] * zs[o*400 + e1];
            }
            __nv_bfloat162 yv = y2[i2];
            float Y0 = (0.5f*yl0 + __bfloat162float(yv.x)) * gt;
            float Y1 = (0.5f*yl1 + __bfloat162float(yv.y)) * gt;
            y2[i2] = __floats2bfloat162_rn(Y0, Y1);
            lsy += Y0 + Y1;
            lsyy += Y0*Y0 + Y1*Y1;
        }
        #pragma unroll
        for (int off = 16; off > 0; off >>= 1) {
            lsy  += __shfl_down_sync(0xffffffffu, lsy, off);
            lsyy += __shfl_down_sync(0xffffffffu, lsyy, off);
        }
        if (lane == 0) {
            atomicAdd(&g_SY[cc], lsy);
            atomicAdd(&g_SYY[cc], lsyy);
        }
    }
}

// ---------------- K9: out = relu(BN(Yg) + x), BN inline ----------------
__global__ void k9(const float* __restrict__ x,
                   const float* __restrict__ bn_g, const float* __restrict__ bn_b,
                   float* __restrict__ out) {
    int i = blockIdx.x * 256 + threadIdx.x;
    if (i >= 3276800) return;
    int c = (i / 800) & 63;
    const float icnt = 1.f/204800.f;
    float mu = g_SY[c] * icnt;
    float var = g_SYY[c] * icnt - mu*mu;
    float sc = bn_g[c] * rsqrtf(var + 1e-5f);
    float sh = bn_b[c] - mu*sc;
    const __nv_bfloat162* y2 = reinterpret_cast<const __nv_bfloat162*>(g_y1);
    __nv_bfloat162 ya = y2[i*2], yb = y2[i*2 + 1];
    float4 xv = reinterpret_cast<const float4*>(x)[i];
    float4 o;
    o.x = fmaxf(__bfloat162float(ya.x)*sc + sh + xv.x, 0.f);
    o.y = fmaxf(__bfloat162float(ya.y)*sc + sh + xv.y, 0.f);
    o.z = fmaxf(__bfloat162float(yb.x)*sc + sh + xv.z, 0.f);
    o.w = fmaxf(__bfloat162float(yb.y)*sc + sh + xv.w, 0.f);
    reinterpret_cast<float4*>(out)[i] = o;
}

// ---------------- launch ----------------
extern "C" void kernel_launch(void* const* d_in, const int* in_sizes, int n_in,
                              void* d_out, int out_size) {
    const float* x     = (const float*)d_in[0];
    const float* Dpap  = (const float*)d_in[1];
    const float* pa    = (const float*)d_in[2];
    const float* DecA  = (const float*)d_in[3];
    const float* A1buf = (const float*)d_in[4];
    const float* Wp    = (const float*)d_in[5];
    const float* bp    = (const float*)d_in[6];
    const float* Ws    = (const float*)d_in[7];
    const float* bs    = (const float*)d_in[8];
    const float* W1    = (const float*)d_in[9];
    const float* b1    = (const float*)d_in[10];
    const float* W2    = (const float*)d_in[11];
    const float* b2    = (const float*)d_in[12];
    const float* We    = (const float*)d_in[13];
    const float* be    = (const float*)d_in[14];
    const float* wt1   = (const float*)d_in[15];
    const float* wt2   = (const float*)d_in[16];
    const float* wtw1  = (const float*)d_in[17];
    const float* wtw2  = (const float*)d_in[18];
    const float* wtw11 = (const float*)d_in[19];
    const float* wtw21 = (const float*)d_in[20];
    const float* ws1   = (const float*)d_in[21];
    const float* ws2   = (const float*)d_in[22];
    const float* kca   = (const float*)d_in[23];
    const float* bn_g  = (const float*)d_in[24];
    const float* bn_b  = (const float*)d_in[25];
    float* out = (float*)d_out;

    cudaFuncSetAttribute(k5, cudaFuncAttributeMaxDynamicSharedMemorySize,
                         K5_SMEM_BYTES);

    k0z<<<400, 256>>>(W2, Ws, b2, bs, Wp, bp, Dpap, pa, DecA, A1buf);
    k1<<<dim3(64, 16), 512>>>(x, Wp, bp);
    k2<<<64, 256>>>(wt1, wt2, wtw1, wtw2, wtw11, wtw21);
    k5<<<dim3(64, 16), 512, K5_SMEM_BYTES>>>(x);
    k4<<<64, 256>>>(W1, b1);
    k6<<<64, 128>>>(ws1, ws2, We, be, kca);
    k7<<<dim3(64, 8), 256>>>(We, be);
    k9<<<12800, 256>>>(x, bn_g, bn_b, out);
}